// round 14
// baseline (speedup 1.0000x reference)
#include <cuda_runtime.h>
#include <cuda_bf16.h>
#include <math.h>
#include <stdint.h>

#define P_N 256
#define L_N 64
#define I_DIM 512
#define H_DIM 1024
#define G4 4096
#define ROWS (P_N * L_N)  // 16384

// ---- scratch ----
__device__ __align__(128) __nv_bfloat16 g_xWb[(size_t)ROWS * G4];   // TIME-MAJOR row=t*256+p, bf16
__device__ __align__(128) uint8_t g_x8[(size_t)ROWS * I_DIM];       // fp8 e4m3, x*64
__device__ __align__(128) uint8_t g_Whh8[(size_t)G4 * H_DIM];       // fp8, permuted rows, w*64
__device__ __align__(128) uint8_t g_Wih8[(size_t)G4 * I_DIM];       // fp8, permuted rows, w*64
__device__ __align__(128) __nv_bfloat16 g_Wv_b[(size_t)H_DIM * H_DIM];
__device__ __align__(128) __nv_bfloat16 g_Wout_b[(size_t)H_DIM * H_DIM];
__device__ float g_bias_p[G4];
__device__ __align__(128) uint8_t g_h8[2][P_N * H_DIM];             // hidden fp8, h*16
__device__ float g_c[P_N * H_DIM];
__device__ __align__(128) __nv_bfloat16 g_final_b[P_N * H_DIM];     // sorted rows, bf16
__device__ __align__(128) __nv_bfloat16 g_vb[P_N * H_DIM];
__device__ float g_attn[P_N * H_DIM];
__device__ float g_pooled[H_DIM];
__device__ int g_perm[P_N];
__device__ int g_lens[P_N];      // lengths sorted descending

__device__ __forceinline__ float sigm(float x) { return 1.0f / (1.0f + expf(-x)); }

__device__ __forceinline__ uint32_t smem_u32(const void* p) {
    uint32_t a;
    asm("{ .reg .u64 t; cvta.to.shared.u64 t, %1; cvt.u32.u64 %0, t; }" : "=r"(a) : "l"(p));
    return a;
}
__device__ __forceinline__ uint32_t swz(uint32_t base, int row, int seg) {
    return base + (uint32_t)row * 128u + (uint32_t)((seg ^ (row & 7)) << 4);
}
__device__ __forceinline__ void cpa16(uint32_t dst, const void* src) {
    asm volatile("cp.async.ca.shared.global [%0], [%1], 16;" :: "r"(dst), "l"(src) : "memory");
}
#define CP_COMMIT() asm volatile("cp.async.commit_group;" ::: "memory")
#define CP_WAIT(n)  asm volatile("cp.async.wait_group " #n ";" ::: "memory")
#define LDM_X4(r0, r1, r2, r3, a)                                                       \
    asm volatile("ldmatrix.sync.aligned.m8n8.x4.shared.b16 {%0,%1,%2,%3}, [%4];"        \
                 : "=r"(r0), "=r"(r1), "=r"(r2), "=r"(r3) : "r"(a))

__device__ __forceinline__ void mmafp8(float* c, const uint32_t* a, const uint32_t* b) {
    asm volatile(
        "mma.sync.aligned.m16n8k32.row.col.f32.e4m3.e4m3.f32 "
        "{%0,%1,%2,%3}, {%4,%5,%6,%7}, {%8,%9}, {%0,%1,%2,%3};"
        : "+f"(c[0]), "+f"(c[1]), "+f"(c[2]), "+f"(c[3])
        : "r"(a[0]), "r"(a[1]), "r"(a[2]), "r"(a[3]), "r"(b[0]), "r"(b[1]));
}
__device__ __forceinline__ void mmabf(float* c, const uint32_t* a, const uint32_t* b) {
    asm volatile(
        "mma.sync.aligned.m16n8k16.row.col.f32.bf16.bf16.f32 "
        "{%0,%1,%2,%3}, {%4,%5,%6,%7}, {%8,%9}, {%0,%1,%2,%3};"
        : "+f"(c[0]), "+f"(c[1]), "+f"(c[2]), "+f"(c[3])
        : "r"(a[0]), "r"(a[1]), "r"(a[2]), "r"(a[3]), "r"(b[0]), "r"(b[1]));
}

// pack 4 floats -> 4 e4m3 bytes; first cvt operand lands in HIGH byte
__device__ __forceinline__ uint32_t pack_e4m3(float a, float b, float c, float d) {
    uint16_t lo, hi;
    asm("cvt.rn.satfinite.e4m3x2.f32 %0, %1, %2;" : "=h"(lo) : "f"(b), "f"(a));
    asm("cvt.rn.satfinite.e4m3x2.f32 %0, %1, %2;" : "=h"(hi) : "f"(d), "f"(c));
    return (uint32_t)lo | ((uint32_t)hi << 16);
}
__device__ __forceinline__ uint16_t pack2_e4m3(float a, float b) {
    uint16_t lo;
    asm("cvt.rn.satfinite.e4m3x2.f32 %0, %1, %2;" : "=h"(lo) : "f"(b), "f"(a));
    return lo;
}

// =================== prep ===================
__global__ void sort_paths(const int* __restrict__ lengths) {
    __shared__ int cnt[L_N + 1];
    const int tid = threadIdx.x;
    if (tid <= L_N) cnt[tid] = 0;
    __syncthreads();
    const int len = lengths[tid];
    atomicAdd(&cnt[len], 1);
    __syncthreads();
    if (tid == 0) {
        int acc = 0;
        for (int l = L_N; l >= 1; l--) { const int c = cnt[l]; cnt[l] = acc; acc += c; }
    }
    __syncthreads();
    const int pos = atomicAdd(&cnt[len], 1);
    g_perm[pos] = tid;
    g_lens[pos] = len;
}

__global__ void zero_hc() {
    int i = blockIdx.x * blockDim.x + threadIdx.x;
    if (i < P_N * H_DIM) { g_h8[0][i] = 0; g_c[i] = 0.0f; }
}

// fused: blocks [0,4096) permute+fp8 LSTM weights; [4096,6144) convert Wv/Wout to bf16
__global__ void permute_weights(const float* __restrict__ Whh, const float* __restrict__ Wih,
                                const float* __restrict__ b_ih, const float* __restrict__ b_hh,
                                const float* __restrict__ Wv, const float* __restrict__ Wout) {
    const int r = blockIdx.x;
    if (r < G4) {
        const int q = (r >> 3) & 3;
        const int j = (r >> 5) * 8 + (r & 7);
        const int orig = q * H_DIM + j;
        const float4* s1 = (const float4*)(Whh + (size_t)orig * H_DIM);
        uint32_t* d1 = (uint32_t*)(g_Whh8 + (size_t)r * H_DIM);
        for (int i = threadIdx.x; i < H_DIM / 4; i += blockDim.x) {
            const float4 v = s1[i];
            d1[i] = pack_e4m3(v.x * 64.f, v.y * 64.f, v.z * 64.f, v.w * 64.f);
        }
        const float4* s2 = (const float4*)(Wih + (size_t)orig * I_DIM);
        uint32_t* d2 = (uint32_t*)(g_Wih8 + (size_t)r * I_DIM);
        for (int i = threadIdx.x; i < I_DIM / 4; i += blockDim.x) {
            const float4 v = s2[i];
            d2[i] = pack_e4m3(v.x * 64.f, v.y * 64.f, v.z * 64.f, v.w * 64.f);
        }
        if (threadIdx.x == 0) g_bias_p[r] = b_ih[orig] + b_hh[orig];
    } else {
        const int rc = r - G4;              // 0..2047
        const int rr = rc & 1023;
        const float4* s = (const float4*)(((rc < 1024) ? Wv : Wout) + (size_t)rr * H_DIM);
        __nv_bfloat162* d = (__nv_bfloat162*)(((rc < 1024) ? g_Wv_b : g_Wout_b) + (size_t)rr * H_DIM);
        for (int i = threadIdx.x; i < H_DIM / 4; i += blockDim.x) {
            const float4 v = s[i];
            d[i * 2 + 0] = __floats2bfloat162_rn(v.x, v.y);
            d[i * 2 + 1] = __floats2bfloat162_rn(v.z, v.w);
        }
    }
}

// gather time-major fp8
__global__ void gather_emb(const int* __restrict__ paths, const float* __restrict__ emb) {
    const int row = blockIdx.x * 2 + (threadIdx.x >> 7);
    const int k4 = (threadIdx.x & 127) * 4;
    const int t = row >> 8, p = row & 255;
    const int tok = paths[g_perm[p] * L_N + t];
    const float4 v = *(const float4*)(emb + (size_t)tok * I_DIM + k4);
    *(uint32_t*)(g_x8 + (size_t)row * I_DIM + k4) =
        pack_e4m3(v.x * 64.f, v.y * 64.f, v.z * 64.f, v.w * 64.f);
}

// =================== embed GEMM (fp8, 64p x 128n tiles, per-(t,quarter) early-exit) ==============
// grid (32 n, 256 m). 8 warps 2m x 4n. K=512 fp8 (4 chunks of 128B). 4 stages x 24KB, occ 2.
#define E_STG2 24576  // A 8KB + B 16KB

__global__ void __launch_bounds__(256, 2) gemm_embed_bf() {
    if (g_lens[(blockIdx.y & 3) * 64] <= (int)(blockIdx.y >> 2)) return;

    extern __shared__ char sm[];
    const uint32_t sb = smem_u32(sm);
    const int tid = threadIdx.x;
    const int lane = tid & 31, wid = tid >> 5;
    const int wm = wid >> 2, wn = wid & 3;        // 2m x 4n
    const int gr = lane >> 2, tg = lane & 3;
    const int m0 = blockIdx.y * 64, n0 = blockIdx.x * 128;

    const int a_row_l = (lane & 7) + ((lane >> 3) & 1) * 8;
    const int a_seg_l = lane >> 4;
    const int b_row_l = wn * 32 + (lane & 7) + (lane >> 4) * 8;
    const int b_seg_l = (lane >> 3) & 1;

    float cfr[2][4][4];
    #pragma unroll
    for (int a = 0; a < 2; a++)
        #pragma unroll
        for (int b = 0; b < 4; b++)
            #pragma unroll
            for (int c = 0; c < 4; c++) cfr[a][b][c] = 0.0f;

    #define E_ISSUE(cc) do {                                                            \
        const uint32_t ab = sb + ((cc) & 3) * E_STG2;                                   \
        const uint32_t bb = ab + 8192;                                                  \
        const int k0 = (cc) * 128;                                                      \
        _Pragma("unroll")                                                               \
        for (int i = 0; i < 2; i++) {                                                   \
            const int idx = tid + i * 256;                                              \
            const int row = idx >> 3, seg = idx & 7;                                    \
            cpa16(swz(ab, row, seg), g_x8 + (size_t)(m0 + row) * I_DIM + k0 + seg * 16);\
        }                                                                               \
        _Pragma("unroll")                                                               \
        for (int i = 0; i < 4; i++) {                                                   \
            const int idx = tid + i * 256;                                              \
            const int row = idx >> 3, seg = idx & 7;                                    \
            cpa16(swz(bb, row, seg),                                                    \
                  g_Wih8 + (size_t)(n0 + row) * I_DIM + k0 + seg * 16);                 \
        }                                                                               \
        CP_COMMIT();                                                                    \
    } while (0)

    E_ISSUE(0); E_ISSUE(1); E_ISSUE(2);

    for (int ch = 0; ch < 4; ch++) {
        if (ch <= 1) CP_WAIT(2);
        else if (ch == 2) CP_WAIT(1);
        else CP_WAIT(0);
        __syncthreads();
        if (ch + 3 < 4) E_ISSUE(ch + 3);

        const uint32_t ab = sb + (ch & 3) * E_STG2;
        const uint32_t bb = ab + 8192;
        #pragma unroll
        for (int s = 0; s < 4; s++) {
            uint32_t af[2][4], bf[4][2];
            #pragma unroll
            for (int mf = 0; mf < 2; mf++)
                LDM_X4(af[mf][0], af[mf][1], af[mf][2], af[mf][3],
                       swz(ab, wm * 32 + mf * 16 + a_row_l, 2 * s + a_seg_l));
            #pragma unroll
            for (int h = 0; h < 2; h++)
                LDM_X4(bf[2 * h][0], bf[2 * h][1], bf[2 * h + 1][0], bf[2 * h + 1][1],
                       swz(bb, b_row_l + h * 16, 2 * s + b_seg_l));
            #pragma unroll
            for (int mf = 0; mf < 2; mf++)
                #pragma unroll
                for (int nf = 0; nf < 4; nf++)
                    mmafp8(cfr[mf][nf], af[mf], bf[nf]);
        }
    }
    #undef E_ISSUE

    const int colw = n0 + wn * 32;
    const float inv = 1.0f / 4096.0f;
    #pragma unroll
    for (int mf = 0; mf < 2; mf++) {
        #pragma unroll
        for (int rr = 0; rr < 2; rr++) {
            const int row = m0 + wm * 32 + mf * 16 + gr + rr * 8;
            __nv_bfloat16* orow = g_xWb + (size_t)row * G4 + colw;
            #pragma unroll
            for (int q = 0; q < 4; q++) {
                const int cl = q * 8 + 2 * tg;
                const float2 bv = *(const float2*)&g_bias_p[colw + cl];
                *(__nv_bfloat162*)(orow + cl) = __floats2bfloat162_rn(
                    cfr[mf][q][rr * 2 + 0] * inv + bv.x, cfr[mf][q][rr * 2 + 1] * inv + bv.y);
            }
        }
    }
}

// =================== LSTM step (fp8, 64x64 tiles, 256B K-chunks, early-exit) ===================
// grid (64 n, 4 m) = 256 CTAs, 8 warps 4m x 2n. K=1024 fp8 as 4 chunks of 256B.
// Stage layout: 128 virtual rows (vrow = row + 64*khalf) x 128B swizzled. 3 stages x 32KB, occ 2.
#define L_STG3 32768  // A 16KB + B 16KB

__global__ void __launch_bounds__(256, 2) lstm_step2(const int step) {
    const int m0 = blockIdx.y * 64;
    if (g_lens[m0] <= step) return;

    extern __shared__ char sm[];
    const uint32_t sb = smem_u32(sm);
    const int tid = threadIdx.x;
    const int lane = tid & 31, wid = tid >> 5;
    const int wm = wid & 3, wn = wid >> 2;        // 4m x 2n
    const int gr = lane >> 2, tg = lane & 3;
    const int n0 = blockIdx.x * 64;

    const uint8_t* __restrict__ A_g = g_h8[step & 1];
    uint8_t* __restrict__ h_next = g_h8[(step & 1) ^ 1];

    const int a_row_l = (lane & 7) + ((lane >> 3) & 1) * 8;
    const int a_seg_l = lane >> 4;
    const int b_row_l = wn * 32 + (lane & 7) + (lane >> 4) * 8;
    const int b_seg_l = (lane >> 3) & 1;

    float cfr[4][4];
    #pragma unroll
    for (int b = 0; b < 4; b++)
        #pragma unroll
        for (int c = 0; c < 4; c++) cfr[b][c] = 0.0f;

    // 256B chunk: vrow = row + 64*khalf; loader covers 128 vrows x 8 segs per operand
    #define L_ISSUE(cc) do {                                                            \
        const uint32_t ab = sb + ((cc) % 3) * L_STG3;                                   \
        const uint32_t bb = ab + 16384;                                                 \
        const int k0 = (cc) * 256;                                                      \
        _Pragma("unroll")                                                               \
        for (int i = 0; i < 4; i++) {                                                   \
            const int idx = tid + i * 256;                                              \
            const int vrow = idx >> 3, seg = idx & 7;                                   \
            const int row = vrow & 63, kh = vrow >> 6;                                  \
            cpa16(swz(ab, vrow, seg),                                                   \
                  A_g + (size_t)(m0 + row) * H_DIM + k0 + kh * 128 + seg * 16);         \
            cpa16(swz(bb, vrow, seg),                                                   \
                  g_Whh8 + (size_t)(n0 + row) * H_DIM + k0 + kh * 128 + seg * 16);      \
        }                                                                               \
        CP_COMMIT();                                                                    \
    } while (0)

    L_ISSUE(0); L_ISSUE(1);

    for (int ch = 0; ch < 4; ch++) {
        if (ch <= 2) CP_WAIT(1);
        else CP_WAIT(0);
        __syncthreads();
        if (ch + 2 < 4) L_ISSUE(ch + 2);

        const uint32_t ab = sb + (ch % 3) * L_STG3;
        const uint32_t bb = ab + 16384;
        #pragma unroll
        for (int s = 0; s < 8; s++) {
            const int khoff = (s >> 2) * 64;          // second 128B half -> vrow +64
            const int ss = s & 3;
            uint32_t af[4], bf[4][2];
            LDM_X4(af[0], af[1], af[2], af[3],
                   swz(ab, wm * 16 + a_row_l + khoff, 2 * ss + a_seg_l));
            #pragma unroll
            for (int h = 0; h < 2; h++)
                LDM_X4(bf[2 * h][0], bf[2 * h][1], bf[2 * h + 1][0], bf[2 * h + 1][1],
                       swz(bb, b_row_l + h * 16 + khoff, 2 * ss + b_seg_l));
            #pragma unroll
            for (int nf = 0; nf < 4; nf++)
                mmafp8(cfr[nf], af, bf[nf]);
        }
    }
    #undef L_ISSUE

    // epilogue: acc = (64 W)·(16 h) -> gate = acc/1024 + xw
    const int colw = n0 + wn * 32;
    const int jpair = (colw >> 5) * 8 + 2 * tg;
    const float inv = 1.0f / 1024.0f;
    #pragma unroll
    for (int rr = 0; rr < 2; rr++) {
        const int p = m0 + wm * 16 + gr + rr * 8;
        const int lenm1 = g_lens[p] - 1;
        const size_t xb = (size_t)(step * 256 + p) * G4 + colw;
        float2 xw[4];
        #pragma unroll
        for (int q = 0; q < 4; q++)
            xw[q] = __bfloat1622float2(*(const __nv_bfloat162*)&g_xWb[xb + q * 8 + 2 * tg]);

        const float gi0 = cfr[0][rr * 2 + 0] * inv + xw[0].x;
        const float gf0 = cfr[1][rr * 2 + 0] * inv + xw[1].x;
        const float gg0 = cfr[2][rr * 2 + 0] * inv + xw[2].x;
        const float go0 = cfr[3][rr * 2 + 0] * inv + xw[3].x;
        const float gi1 = cfr[0][rr * 2 + 1] * inv + xw[0].y;
        const float gf1 = cfr[1][rr * 2 + 1] * inv + xw[1].y;
        const float gg1 = cfr[2][rr * 2 + 1] * inv + xw[2].y;
        const float go1 = cfr[3][rr * 2 + 1] * inv + xw[3].y;

        const int ci = p * H_DIM + jpair;
        const float2 cold = *(const float2*)&g_c[ci];
        const float c0 = sigm(gf0) * cold.x + sigm(gi0) * tanhf(gg0);
        const float c1 = sigm(gf1) * cold.y + sigm(gi1) * tanhf(gg1);
        *(float2*)&g_c[ci] = make_float2(c0, c1);
        const float h0 = sigm(go0) * tanhf(c0);
        const float h1 = sigm(go1) * tanhf(c1);

        *(uint16_t*)&h_next[ci] = pack2_e4m3(h0 * 16.f, h1 * 16.f);
        if (lenm1 == step)
            *(__nv_bfloat162*)&g_final_b[ci] = __floats2bfloat162_rn(h0, h1);
    }
}

// =================== tail projections (bf16 mma, 64x64 tiles, occ 2) ===================
#define T_STG 16384  // A 8KB + B 8KB

__global__ void __launch_bounds__(256, 2) gemm_proj_bf(const float* __restrict__ bias,
                                                       const int sel) {
    extern __shared__ char sm[];
    const uint32_t sb = smem_u32(sm);
    const int tid = threadIdx.x;
    const int lane = tid & 31, wid = tid >> 5;
    const int wm = wid & 3, wn = wid >> 2;        // 4m x 2n
    const int gr = lane >> 2, tg = lane & 3;
    const int m0 = blockIdx.y * 64, n0 = blockIdx.x * 64;

    const __nv_bfloat16* __restrict__ A_g = (sel == 0) ? g_final_b : g_vb;
    const __nv_bfloat16* __restrict__ B_g = (sel == 0) ? g_Wv_b : g_Wout_b;

    const int a_row_l = (lane & 7) + ((lane >> 3) & 1) * 8;
    const int a_seg_l = lane >> 4;
    const int b_row_l = wn * 32 + (lane & 7) + (lane >> 4) * 8;
    const int b_seg_l = (lane >> 3) & 1;

    float cfr[4][4];
    #pragma unroll
    for (int b = 0; b < 4; b++)
        #pragma unroll
        for (int c = 0; c < 4; c++) cfr[b][c] = 0.0f;

    #define P_ISSUE(cc) do {                                                            \
        const uint32_t ab = sb + ((cc) & 3) * T_STG;                                    \
        const uint32_t bb = ab + 8192;                                                  \
        const int k0 = (cc) * 64;                                                       \
        _Pragma("unroll")                                                               \
        for (int i = 0; i < 2; i++) {                                                   \
            const int idx = tid + i * 256;                                              \
            const int row = idx >> 3, seg = idx & 7;                                    \
            cpa16(swz(ab, row, seg), A_g + (size_t)(m0 + row) * H_DIM + k0 + seg * 8);  \
            cpa16(swz(bb, row, seg), B_g + (size_t)(n0 + row) * H_DIM + k0 + seg * 8);  \
        }                                                                               \
        CP_COMMIT();                                                                    \
    } while (0)

    P_ISSUE(0); P_ISSUE(1); P_ISSUE(2);

    for (int ch = 0; ch < 16; ch++) {
        if (ch <= 13) CP_WAIT(2);
        else if (ch == 14) CP_WAIT(1);
        else CP_WAIT(0);
        __syncthreads();
        if (ch + 3 < 16) P_ISSUE(ch + 3);

        const uint32_t ab = sb + (ch & 3) * T_STG;
        const uint32_t bb = ab + 8192;
        #pragma unroll
        for (int s = 0; s < 4; s++) {
            uint32_t af[4], bf[4][2];
            LDM_X4(af[0], af[1], af[2], af[3],
                   swz(ab, wm * 16 + a_row_l, 2 * s + a_seg_l));
            #pragma unroll
            for (int h = 0; h < 2; h++)
                LDM_X4(bf[2 * h][0], bf[2 * h][1], bf[2 * h + 1][0], bf[2 * h + 1][1],
                       swz(bb, b_row_l + h * 16, 2 * s + b_seg_l));
            #pragma unroll
            for (int nf = 0; nf < 4; nf++)
                mmabf(cfr[nf], af, bf[nf]);
        }
    }
    #undef P_ISSUE

    const int colw = n0 + wn * 32;
    #pragma unroll
    for (int rr = 0; rr < 2; rr++) {
        const int row = m0 + wm * 16 + gr + rr * 8;
        #pragma unroll
        for (int q = 0; q < 4; q++) {
            const int cl = q * 8 + 2 * tg;
            const float2 bv = *(const float2*)&bias[colw + cl];
            const float v0 = cfr[q][rr * 2 + 0] + bv.x;
            const float v1 = cfr[q][rr * 2 + 1] + bv.y;
            if (sel == 0)
                *(__nv_bfloat162*)&g_vb[(size_t)row * H_DIM + colw + cl] =
                    __floats2bfloat162_rn(v0, v1);
            else
                *(float2*)&g_attn[(size_t)row * H_DIM + colw + cl] = make_float2(v0, v1);
        }
    }
}

// colmax: 32 blocks x 256 thr; 8 p-slices per column, smem reduce
__global__ void colmax() {
    __shared__ float red[8][32];
    const int j = blockIdx.x * 32 + (threadIdx.x & 31);
    const int sl = threadIdx.x >> 5;
    float m = -INFINITY;
    for (int p = sl * 32; p < sl * 32 + 32; p++)
        m = fmaxf(m, g_attn[(size_t)p * H_DIM + j]);
    red[sl][threadIdx.x & 31] = m;
    __syncthreads();
    if (sl == 0) {
        #pragma unroll
        for (int s = 1; s < 8; s++) m = fmaxf(m, red[s][threadIdx.x & 31]);
        g_pooled[j] = m;
    }
}

__global__ void final_k(const float* __restrict__ W_lin,
                        const float* __restrict__ b_lin, float* __restrict__ out)
{
    __shared__ float r0[256], r1[256];
    const int tid = threadIdx.x;
    float a0 = 0.0f, a1 = 0.0f;
    for (int j = tid; j < H_DIM; j += 256) {
        const float pv = g_pooled[j];
        a0 += pv * W_lin[j];
        a1 += pv * W_lin[H_DIM + j];
    }
    r0[tid] = a0; r1[tid] = a1;
    __syncthreads();
    for (int s = 128; s > 0; s >>= 1) {
        if (tid < s) { r0[tid] += r0[tid + s]; r1[tid] += r1[tid + s]; }
        __syncthreads();
    }
    if (tid == 0) {
        out[0] = sigm(r0[0] + b_lin[0]);
        out[1] = sigm(r1[0] + b_lin[1]);
    }
}

extern "C" void kernel_launch(void* const* d_in, const int* in_sizes, int n_in,
                              void* d_out, int out_size) {
    const int*   paths   = (const int*)d_in[0];
    const int*   lengths = (const int*)d_in[1];
    const float* emb     = (const float*)d_in[2];
    const float* W_ih    = (const float*)d_in[3];
    const float* W_hh    = (const float*)d_in[4];
    const float* b_ih    = (const float*)d_in[5];
    const float* b_hh    = (const float*)d_in[6];
    const float* W_in    = (const float*)d_in[7];
    const float* b_in    = (const float*)d_in[8];
    const float* W_out   = (const float*)d_in[9];
    const float* b_out   = (const float*)d_in[10];
    const float* W_lin   = (const float*)d_in[11];
    const float* b_lin   = (const float*)d_in[12];
    float* out = (float*)d_out;

    static int attr_done = 0;
    if (!attr_done) {
        cudaFuncSetAttribute(gemm_embed_bf, cudaFuncAttributeMaxDynamicSharedMemorySize, 4 * E_STG2);
        cudaFuncSetAttribute(lstm_step2,    cudaFuncAttributeMaxDynamicSharedMemorySize, 3 * L_STG3);
        cudaFuncSetAttribute(gemm_proj_bf,  cudaFuncAttributeMaxDynamicSharedMemorySize, 4 * T_STG);
        attr_done = 1;
    }

    sort_paths<<<1, 256>>>(lengths);
    permute_weights<<<6144, 128>>>(W_hh, W_ih, b_ih, b_hh,
                                   W_in + (size_t)2 * H_DIM * H_DIM, W_out);
    gather_emb<<<ROWS / 2, 256>>>(paths, emb);
    zero_hc<<<(P_N * H_DIM + 255) / 256, 256>>>();
    gemm_embed_bf<<<dim3(G4 / 128, ROWS / 64), 256, 4 * E_STG2>>>();
    for (int t = 0; t < L_N; t++)
        lstm_step2<<<dim3(G4 / 64, P_N / 64), 256, 3 * L_STG3>>>(t);
    // seq_len==1 attention: softmax == 1, ctx == v; q/k projections are dead code
    gemm_proj_bf<<<dim3(H_DIM / 64, P_N / 64), 256, 4 * T_STG>>>(b_in + 2 * H_DIM, 0);
    gemm_proj_bf<<<dim3(H_DIM / 64, P_N / 64), 256, 4 * T_STG>>>(b_out, 1);
    colmax<<<H_DIM / 32, 256>>>();
    final_k<<<1, 256>>>(W_lin, b_lin, out);
}

// round 15
// speedup vs baseline: 1.0467x; 1.0467x over previous
#include <cuda_runtime.h>
#include <cuda_bf16.h>
#include <math.h>
#include <stdint.h>

#define P_N 256
#define L_N 64
#define I_DIM 512
#define H_DIM 1024
#define G4 4096
#define ROWS (P_N * L_N)  // 16384

// ---- scratch ----
__device__ __align__(128) __nv_bfloat16 g_xWb[(size_t)ROWS * G4];   // TIME-MAJOR row=t*256+p, bf16
__device__ __align__(128) uint8_t g_x8[(size_t)ROWS * I_DIM];       // fp8 e4m3, x*64
__device__ __align__(128) uint8_t g_Whh8[(size_t)G4 * H_DIM];       // fp8, permuted rows, w*64
__device__ __align__(128) uint8_t g_Wih8[(size_t)G4 * I_DIM];       // fp8, permuted rows, w*64
__device__ __align__(128) __nv_bfloat16 g_Wv_b[(size_t)H_DIM * H_DIM];
__device__ __align__(128) __nv_bfloat16 g_Wout_b[(size_t)H_DIM * H_DIM];
__device__ float g_bias_p[G4];
__device__ __align__(128) uint8_t g_h8[2][P_N * H_DIM];             // hidden fp8, h*16
__device__ float g_c[P_N * H_DIM];
__device__ __align__(128) __nv_bfloat16 g_final_b[P_N * H_DIM];     // sorted rows, bf16
__device__ __align__(128) __nv_bfloat16 g_vb[P_N * H_DIM];
__device__ float g_attn[P_N * H_DIM];
__device__ float g_pooled[H_DIM];
__device__ int g_perm[P_N];
__device__ int g_lens[P_N];      // lengths sorted descending

__device__ __forceinline__ float sigm(float x) { return 1.0f / (1.0f + expf(-x)); }

__device__ __forceinline__ uint32_t smem_u32(const void* p) {
    uint32_t a;
    asm("{ .reg .u64 t; cvta.to.shared.u64 t, %1; cvt.u32.u64 %0, t; }" : "=r"(a) : "l"(p));
    return a;
}
__device__ __forceinline__ uint32_t swz(uint32_t base, int row, int seg) {
    return base + (uint32_t)row * 128u + (uint32_t)((seg ^ (row & 7)) << 4);
}
__device__ __forceinline__ void cpa16(uint32_t dst, const void* src) {
    asm volatile("cp.async.ca.shared.global [%0], [%1], 16;" :: "r"(dst), "l"(src) : "memory");
}
#define CP_COMMIT() asm volatile("cp.async.commit_group;" ::: "memory")
#define CP_WAIT(n)  asm volatile("cp.async.wait_group " #n ";" ::: "memory")
#define LDM_X4(r0, r1, r2, r3, a)                                                       \
    asm volatile("ldmatrix.sync.aligned.m8n8.x4.shared.b16 {%0,%1,%2,%3}, [%4];"        \
                 : "=r"(r0), "=r"(r1), "=r"(r2), "=r"(r3) : "r"(a))

__device__ __forceinline__ void mmafp8(float* c, const uint32_t* a, const uint32_t* b) {
    asm volatile(
        "mma.sync.aligned.m16n8k32.row.col.f32.e4m3.e4m3.f32 "
        "{%0,%1,%2,%3}, {%4,%5,%6,%7}, {%8,%9}, {%0,%1,%2,%3};"
        : "+f"(c[0]), "+f"(c[1]), "+f"(c[2]), "+f"(c[3])
        : "r"(a[0]), "r"(a[1]), "r"(a[2]), "r"(a[3]), "r"(b[0]), "r"(b[1]));
}
__device__ __forceinline__ void mmabf(float* c, const uint32_t* a, const uint32_t* b) {
    asm volatile(
        "mma.sync.aligned.m16n8k16.row.col.f32.bf16.bf16.f32 "
        "{%0,%1,%2,%3}, {%4,%5,%6,%7}, {%8,%9}, {%0,%1,%2,%3};"
        : "+f"(c[0]), "+f"(c[1]), "+f"(c[2]), "+f"(c[3])
        : "r"(a[0]), "r"(a[1]), "r"(a[2]), "r"(a[3]), "r"(b[0]), "r"(b[1]));
}

// pack 4 floats -> 4 e4m3 bytes; first cvt operand lands in HIGH byte
__device__ __forceinline__ uint32_t pack_e4m3(float a, float b, float c, float d) {
    uint16_t lo, hi;
    asm("cvt.rn.satfinite.e4m3x2.f32 %0, %1, %2;" : "=h"(lo) : "f"(b), "f"(a));
    asm("cvt.rn.satfinite.e4m3x2.f32 %0, %1, %2;" : "=h"(hi) : "f"(d), "f"(c));
    return (uint32_t)lo | ((uint32_t)hi << 16);
}
__device__ __forceinline__ uint16_t pack2_e4m3(float a, float b) {
    uint16_t lo;
    asm("cvt.rn.satfinite.e4m3x2.f32 %0, %1, %2;" : "=h"(lo) : "f"(b), "f"(a));
    return lo;
}

// =================== prep ===================
__global__ void sort_paths(const int* __restrict__ lengths) {
    __shared__ int cnt[L_N + 1];
    const int tid = threadIdx.x;
    if (tid <= L_N) cnt[tid] = 0;
    __syncthreads();
    const int len = lengths[tid];
    atomicAdd(&cnt[len], 1);
    __syncthreads();
    if (tid == 0) {
        int acc = 0;
        for (int l = L_N; l >= 1; l--) { const int c = cnt[l]; cnt[l] = acc; acc += c; }
    }
    __syncthreads();
    const int pos = atomicAdd(&cnt[len], 1);
    g_perm[pos] = tid;
    g_lens[pos] = len;
}

__global__ void zero_hc() {
    int i = blockIdx.x * blockDim.x + threadIdx.x;
    if (i < P_N * H_DIM) { g_h8[0][i] = 0; g_c[i] = 0.0f; }
}

// fused: blocks [0,4096) permute+fp8 LSTM weights; [4096,6144) convert Wv/Wout to bf16
__global__ void permute_weights(const float* __restrict__ Whh, const float* __restrict__ Wih,
                                const float* __restrict__ b_ih, const float* __restrict__ b_hh,
                                const float* __restrict__ Wv, const float* __restrict__ Wout) {
    const int r = blockIdx.x;
    if (r < G4) {
        const int q = (r >> 3) & 3;
        const int j = (r >> 5) * 8 + (r & 7);
        const int orig = q * H_DIM + j;
        const float4* s1 = (const float4*)(Whh + (size_t)orig * H_DIM);
        uint32_t* d1 = (uint32_t*)(g_Whh8 + (size_t)r * H_DIM);
        for (int i = threadIdx.x; i < H_DIM / 4; i += blockDim.x) {
            const float4 v = s1[i];
            d1[i] = pack_e4m3(v.x * 64.f, v.y * 64.f, v.z * 64.f, v.w * 64.f);
        }
        const float4* s2 = (const float4*)(Wih + (size_t)orig * I_DIM);
        uint32_t* d2 = (uint32_t*)(g_Wih8 + (size_t)r * I_DIM);
        for (int i = threadIdx.x; i < I_DIM / 4; i += blockDim.x) {
            const float4 v = s2[i];
            d2[i] = pack_e4m3(v.x * 64.f, v.y * 64.f, v.z * 64.f, v.w * 64.f);
        }
        if (threadIdx.x == 0) g_bias_p[r] = b_ih[orig] + b_hh[orig];
    } else {
        const int rc = r - G4;              // 0..2047
        const int rr = rc & 1023;
        const float4* s = (const float4*)(((rc < 1024) ? Wv : Wout) + (size_t)rr * H_DIM);
        __nv_bfloat162* d = (__nv_bfloat162*)(((rc < 1024) ? g_Wv_b : g_Wout_b) + (size_t)rr * H_DIM);
        for (int i = threadIdx.x; i < H_DIM / 4; i += blockDim.x) {
            const float4 v = s[i];
            d[i * 2 + 0] = __floats2bfloat162_rn(v.x, v.y);
            d[i * 2 + 1] = __floats2bfloat162_rn(v.z, v.w);
        }
    }
}

// gather time-major fp8
__global__ void gather_emb(const int* __restrict__ paths, const float* __restrict__ emb) {
    const int row = blockIdx.x * 2 + (threadIdx.x >> 7);
    const int k4 = (threadIdx.x & 127) * 4;
    const int t = row >> 8, p = row & 255;
    const int tok = paths[g_perm[p] * L_N + t];
    const float4 v = *(const float4*)(emb + (size_t)tok * I_DIM + k4);
    *(uint32_t*)(g_x8 + (size_t)row * I_DIM + k4) =
        pack_e4m3(v.x * 64.f, v.y * 64.f, v.z * 64.f, v.w * 64.f);
}

// =================== embed GEMM (fp8, 64p x 128n tiles, per-(t,quarter) early-exit) ==============
// grid (32 n, 256 m). 8 warps 2m x 4n. K=512 fp8 (4 chunks of 128B). 4 stages x 24KB, occ 2.
#define E_STG2 24576  // A 8KB + B 16KB

__global__ void __launch_bounds__(256, 2) gemm_embed_bf() {
    if (g_lens[(blockIdx.y & 3) * 64] <= (int)(blockIdx.y >> 2)) return;

    extern __shared__ char sm[];
    const uint32_t sb = smem_u32(sm);
    const int tid = threadIdx.x;
    const int lane = tid & 31, wid = tid >> 5;
    const int wm = wid >> 2, wn = wid & 3;        // 2m x 4n
    const int gr = lane >> 2, tg = lane & 3;
    const int m0 = blockIdx.y * 64, n0 = blockIdx.x * 128;

    const int a_row_l = (lane & 7) + ((lane >> 3) & 1) * 8;
    const int a_seg_l = lane >> 4;
    const int b_row_l = wn * 32 + (lane & 7) + (lane >> 4) * 8;
    const int b_seg_l = (lane >> 3) & 1;

    float cfr[2][4][4];
    #pragma unroll
    for (int a = 0; a < 2; a++)
        #pragma unroll
        for (int b = 0; b < 4; b++)
            #pragma unroll
            for (int c = 0; c < 4; c++) cfr[a][b][c] = 0.0f;

    #define E_ISSUE(cc) do {                                                            \
        const uint32_t ab = sb + ((cc) & 3) * E_STG2;                                   \
        const uint32_t bb = ab + 8192;                                                  \
        const int k0 = (cc) * 128;                                                      \
        _Pragma("unroll")                                                               \
        for (int i = 0; i < 2; i++) {                                                   \
            const int idx = tid + i * 256;                                              \
            const int row = idx >> 3, seg = idx & 7;                                    \
            cpa16(swz(ab, row, seg), g_x8 + (size_t)(m0 + row) * I_DIM + k0 + seg * 16);\
        }                                                                               \
        _Pragma("unroll")                                                               \
        for (int i = 0; i < 4; i++) {                                                   \
            const int idx = tid + i * 256;                                              \
            const int row = idx >> 3, seg = idx & 7;                                    \
            cpa16(swz(bb, row, seg),                                                    \
                  g_Wih8 + (size_t)(n0 + row) * I_DIM + k0 + seg * 16);                 \
        }                                                                               \
        CP_COMMIT();                                                                    \
    } while (0)

    E_ISSUE(0); E_ISSUE(1); E_ISSUE(2);

    for (int ch = 0; ch < 4; ch++) {
        if (ch <= 1) CP_WAIT(2);
        else if (ch == 2) CP_WAIT(1);
        else CP_WAIT(0);
        __syncthreads();
        if (ch + 3 < 4) E_ISSUE(ch + 3);

        const uint32_t ab = sb + (ch & 3) * E_STG2;
        const uint32_t bb = ab + 8192;
        #pragma unroll
        for (int s = 0; s < 4; s++) {
            uint32_t af[2][4], bf[4][2];
            #pragma unroll
            for (int mf = 0; mf < 2; mf++)
                LDM_X4(af[mf][0], af[mf][1], af[mf][2], af[mf][3],
                       swz(ab, wm * 32 + mf * 16 + a_row_l, 2 * s + a_seg_l));
            #pragma unroll
            for (int h = 0; h < 2; h++)
                LDM_X4(bf[2 * h][0], bf[2 * h][1], bf[2 * h + 1][0], bf[2 * h + 1][1],
                       swz(bb, b_row_l + h * 16, 2 * s + b_seg_l));
            #pragma unroll
            for (int mf = 0; mf < 2; mf++)
                #pragma unroll
                for (int nf = 0; nf < 4; nf++)
                    mmafp8(cfr[mf][nf], af[mf], bf[nf]);
        }
    }
    #undef E_ISSUE

    const int colw = n0 + wn * 32;
    const float inv = 1.0f / 4096.0f;
    #pragma unroll
    for (int mf = 0; mf < 2; mf++) {
        #pragma unroll
        for (int rr = 0; rr < 2; rr++) {
            const int row = m0 + wm * 32 + mf * 16 + gr + rr * 8;
            __nv_bfloat16* orow = g_xWb + (size_t)row * G4 + colw;
            #pragma unroll
            for (int q = 0; q < 4; q++) {
                const int cl = q * 8 + 2 * tg;
                const float2 bv = *(const float2*)&g_bias_p[colw + cl];
                *(__nv_bfloat162*)(orow + cl) = __floats2bfloat162_rn(
                    cfr[mf][q][rr * 2 + 0] * inv + bv.x, cfr[mf][q][rr * 2 + 1] * inv + bv.y);
            }
        }
    }
}

// =================== LSTM step (fp8, R13-proven: 64x64 tiles, 128B chunks, 4 stages, occ 2) =====
// grid (64 n, 4 m) = 256 CTAs, 8 warps 4m x 2n. K=1024 fp8 (8 chunks of 128B).
#define L_STG2 16384  // A 8KB + B 8KB

__global__ void __launch_bounds__(256, 2) lstm_step2(const int step) {
    const int m0 = blockIdx.y * 64;
    if (g_lens[m0] <= step) return;

    extern __shared__ char sm[];
    const uint32_t sb = smem_u32(sm);
    const int tid = threadIdx.x;
    const int lane = tid & 31, wid = tid >> 5;
    const int wm = wid & 3, wn = wid >> 2;        // 4m x 2n
    const int gr = lane >> 2, tg = lane & 3;
    const int n0 = blockIdx.x * 64;

    const uint8_t* __restrict__ A_g = g_h8[step & 1];
    uint8_t* __restrict__ h_next = g_h8[(step & 1) ^ 1];

    const int a_row_l = (lane & 7) + ((lane >> 3) & 1) * 8;
    const int a_seg_l = lane >> 4;
    const int b_row_l = wn * 32 + (lane & 7) + (lane >> 4) * 8;
    const int b_seg_l = (lane >> 3) & 1;

    float cfr[4][4];
    #pragma unroll
    for (int b = 0; b < 4; b++)
        #pragma unroll
        for (int c = 0; c < 4; c++) cfr[b][c] = 0.0f;

    #define L_ISSUE(cc) do {                                                            \
        const uint32_t ab = sb + ((cc) & 3) * L_STG2;                                   \
        const uint32_t bb = ab + 8192;                                                  \
        const int k0 = (cc) * 128;                                                      \
        _Pragma("unroll")                                                               \
        for (int i = 0; i < 2; i++) {                                                   \
            const int idx = tid + i * 256;                                              \
            const int row = idx >> 3, seg = idx & 7;                                    \
            cpa16(swz(ab, row, seg), A_g + (size_t)(m0 + row) * H_DIM + k0 + seg * 16); \
            cpa16(swz(bb, row, seg),                                                    \
                  g_Whh8 + (size_t)(n0 + row) * H_DIM + k0 + seg * 16);                 \
        }                                                                               \
        CP_COMMIT();                                                                    \
    } while (0)

    L_ISSUE(0); L_ISSUE(1); L_ISSUE(2);

    for (int ch = 0; ch < 8; ch++) {
        if (ch <= 5) CP_WAIT(2);
        else if (ch == 6) CP_WAIT(1);
        else CP_WAIT(0);
        __syncthreads();
        if (ch + 3 < 8) L_ISSUE(ch + 3);

        const uint32_t ab = sb + (ch & 3) * L_STG2;
        const uint32_t bb = ab + 8192;
        #pragma unroll
        for (int s = 0; s < 4; s++) {
            uint32_t af[4], bf[4][2];
            LDM_X4(af[0], af[1], af[2], af[3],
                   swz(ab, wm * 16 + a_row_l, 2 * s + a_seg_l));
            #pragma unroll
            for (int h = 0; h < 2; h++)
                LDM_X4(bf[2 * h][0], bf[2 * h][1], bf[2 * h + 1][0], bf[2 * h + 1][1],
                       swz(bb, b_row_l + h * 16, 2 * s + b_seg_l));
            #pragma unroll
            for (int nf = 0; nf < 4; nf++)
                mmafp8(cfr[nf], af, bf[nf]);
        }
    }
    #undef L_ISSUE

    // epilogue: acc = (64 W)·(16 h) -> gate = acc/1024 + xw
    const int colw = n0 + wn * 32;
    const int jpair = (colw >> 5) * 8 + 2 * tg;
    const float inv = 1.0f / 1024.0f;
    #pragma unroll
    for (int rr = 0; rr < 2; rr++) {
        const int p = m0 + wm * 16 + gr + rr * 8;
        const int lenm1 = g_lens[p] - 1;
        const size_t xb = (size_t)(step * 256 + p) * G4 + colw;
        float2 xw[4];
        #pragma unroll
        for (int q = 0; q < 4; q++)
            xw[q] = __bfloat1622float2(*(const __nv_bfloat162*)&g_xWb[xb + q * 8 + 2 * tg]);

        const float gi0 = cfr[0][rr * 2 + 0] * inv + xw[0].x;
        const float gf0 = cfr[1][rr * 2 + 0] * inv + xw[1].x;
        const float gg0 = cfr[2][rr * 2 + 0] * inv + xw[2].x;
        const float go0 = cfr[3][rr * 2 + 0] * inv + xw[3].x;
        const float gi1 = cfr[0][rr * 2 + 1] * inv + xw[0].y;
        const float gf1 = cfr[1][rr * 2 + 1] * inv + xw[1].y;
        const float gg1 = cfr[2][rr * 2 + 1] * inv + xw[2].y;
        const float go1 = cfr[3][rr * 2 + 1] * inv + xw[3].y;

        const int ci = p * H_DIM + jpair;
        const float2 cold = *(const float2*)&g_c[ci];
        const float c0 = sigm(gf0) * cold.x + sigm(gi0) * tanhf(gg0);
        const float c1 = sigm(gf1) * cold.y + sigm(gi1) * tanhf(gg1);
        *(float2*)&g_c[ci] = make_float2(c0, c1);
        const float h0 = sigm(go0) * tanhf(c0);
        const float h1 = sigm(go1) * tanhf(c1);

        *(uint16_t*)&h_next[ci] = pack2_e4m3(h0 * 16.f, h1 * 16.f);
        if (lenm1 == step)
            *(__nv_bfloat162*)&g_final_b[ci] = __floats2bfloat162_rn(h0, h1);
    }
}

// =================== tail projections (bf16 mma, 64x64 tiles, occ 2) ===================
#define T_STG 16384  // A 8KB + B 8KB

__global__ void __launch_bounds__(256, 2) gemm_proj_bf(const float* __restrict__ bias,
                                                       const int sel) {
    extern __shared__ char sm[];
    const uint32_t sb = smem_u32(sm);
    const int tid = threadIdx.x;
    const int lane = tid & 31, wid = tid >> 5;
    const int wm = wid & 3, wn = wid >> 2;        // 4m x 2n
    const int gr = lane >> 2, tg = lane & 3;
    const int m0 = blockIdx.y * 64, n0 = blockIdx.x * 64;

    const __nv_bfloat16* __restrict__ A_g = (sel == 0) ? g_final_b : g_vb;
    const __nv_bfloat16* __restrict__ B_g = (sel == 0) ? g_Wv_b : g_Wout_b;

    const int a_row_l = (lane & 7) + ((lane >> 3) & 1) * 8;
    const int a_seg_l = lane >> 4;
    const int b_row_l = wn * 32 + (lane & 7) + (lane >> 4) * 8;
    const int b_seg_l = (lane >> 3) & 1;

    float cfr[4][4];
    #pragma unroll
    for (int b = 0; b < 4; b++)
        #pragma unroll
        for (int c = 0; c < 4; c++) cfr[b][c] = 0.0f;

    #define P_ISSUE(cc) do {                                                            \
        const uint32_t ab = sb + ((cc) & 3) * T_STG;                                    \
        const uint32_t bb = ab + 8192;                                                  \
        const int k0 = (cc) * 64;                                                       \
        _Pragma("unroll")                                                               \
        for (int i = 0; i < 2; i++) {                                                   \
            const int idx = tid + i * 256;                                              \
            const int row = idx >> 3, seg = idx & 7;                                    \
            cpa16(swz(ab, row, seg), A_g + (size_t)(m0 + row) * H_DIM + k0 + seg * 8);  \
            cpa16(swz(bb, row, seg), B_g + (size_t)(n0 + row) * H_DIM + k0 + seg * 8);  \
        }                                                                               \
        CP_COMMIT();                                                                    \
    } while (0)

    P_ISSUE(0); P_ISSUE(1); P_ISSUE(2);

    for (int ch = 0; ch < 16; ch++) {
        if (ch <= 13) CP_WAIT(2);
        else if (ch == 14) CP_WAIT(1);
        else CP_WAIT(0);
        __syncthreads();
        if (ch + 3 < 16) P_ISSUE(ch + 3);

        const uint32_t ab = sb + (ch & 3) * T_STG;
        const uint32_t bb = ab + 8192;
        #pragma unroll
        for (int s = 0; s < 4; s++) {
            uint32_t af[4], bf[4][2];
            LDM_X4(af[0], af[1], af[2], af[3],
                   swz(ab, wm * 16 + a_row_l, 2 * s + a_seg_l));
            #pragma unroll
            for (int h = 0; h < 2; h++)
                LDM_X4(bf[2 * h][0], bf[2 * h][1], bf[2 * h + 1][0], bf[2 * h + 1][1],
                       swz(bb, b_row_l + h * 16, 2 * s + b_seg_l));
            #pragma unroll
            for (int nf = 0; nf < 4; nf++)
                mmabf(cfr[nf], af, bf[nf]);
        }
    }
    #undef P_ISSUE

    const int colw = n0 + wn * 32;
    #pragma unroll
    for (int rr = 0; rr < 2; rr++) {
        const int row = m0 + wm * 16 + gr + rr * 8;
        #pragma unroll
        for (int q = 0; q < 4; q++) {
            const int cl = q * 8 + 2 * tg;
            const float2 bv = *(const float2*)&bias[colw + cl];
            const float v0 = cfr[q][rr * 2 + 0] + bv.x;
            const float v1 = cfr[q][rr * 2 + 1] + bv.y;
            if (sel == 0)
                *(__nv_bfloat162*)&g_vb[(size_t)row * H_DIM + colw + cl] =
                    __floats2bfloat162_rn(v0, v1);
            else
                *(float2*)&g_attn[(size_t)row * H_DIM + colw + cl] = make_float2(v0, v1);
        }
    }
}

// colmax: 32 blocks x 256 thr; 8 p-slices per column, smem reduce
__global__ void colmax() {
    __shared__ float red[8][32];
    const int j = blockIdx.x * 32 + (threadIdx.x & 31);
    const int sl = threadIdx.x >> 5;
    float m = -INFINITY;
    for (int p = sl * 32; p < sl * 32 + 32; p++)
        m = fmaxf(m, g_attn[(size_t)p * H_DIM + j]);
    red[sl][threadIdx.x & 31] = m;
    __syncthreads();
    if (sl == 0) {
        #pragma unroll
        for (int s = 1; s < 8; s++) m = fmaxf(m, red[s][threadIdx.x & 31]);
        g_pooled[j] = m;
    }
}

__global__ void final_k(const float* __restrict__ W_lin,
                        const float* __restrict__ b_lin, float* __restrict__ out)
{
    __shared__ float r0[256], r1[256];
    const int tid = threadIdx.x;
    float a0 = 0.0f, a1 = 0.0f;
    for (int j = tid; j < H_DIM; j += 256) {
        const float pv = g_pooled[j];
        a0 += pv * W_lin[j];
        a1 += pv * W_lin[H_DIM + j];
    }
    r0[tid] = a0; r1[tid] = a1;
    __syncthreads();
    for (int s = 128; s > 0; s >>= 1) {
        if (tid < s) { r0[tid] += r0[tid + s]; r1[tid] += r1[tid + s]; }
        __syncthreads();
    }
    if (tid == 0) {
        out[0] = sigm(r0[0] + b_lin[0]);
        out[1] = sigm(r1[0] + b_lin[1]);
    }
}

extern "C" void kernel_launch(void* const* d_in, const int* in_sizes, int n_in,
                              void* d_out, int out_size) {
    const int*   paths   = (const int*)d_in[0];
    const int*   lengths = (const int*)d_in[1];
    const float* emb     = (const float*)d_in[2];
    const float* W_ih    = (const float*)d_in[3];
    const float* W_hh    = (const float*)d_in[4];
    const float* b_ih    = (const float*)d_in[5];
    const float* b_hh    = (const float*)d_in[6];
    const float* W_in    = (const float*)d_in[7];
    const float* b_in    = (const float*)d_in[8];
    const float* W_out   = (const float*)d_in[9];
    const float* b_out   = (const float*)d_in[10];
    const float* W_lin   = (const float*)d_in[11];
    const float* b_lin   = (const float*)d_in[12];
    float* out = (float*)d_out;

    static int attr_done = 0;
    if (!attr_done) {
        cudaFuncSetAttribute(gemm_embed_bf, cudaFuncAttributeMaxDynamicSharedMemorySize, 4 * E_STG2);
        cudaFuncSetAttribute(lstm_step2,    cudaFuncAttributeMaxDynamicSharedMemorySize, 4 * L_STG2);
        cudaFuncSetAttribute(gemm_proj_bf,  cudaFuncAttributeMaxDynamicSharedMemorySize, 4 * T_STG);
        attr_done = 1;
    }

    sort_paths<<<1, 256>>>(lengths);
    permute_weights<<<6144, 128>>>(W_hh, W_ih, b_ih, b_hh,
                                   W_in + (size_t)2 * H_DIM * H_DIM, W_out);
    gather_emb<<<ROWS / 2, 256>>>(paths, emb);
    zero_hc<<<(P_N * H_DIM + 255) / 256, 256>>>();
    gemm_embed_bf<<<dim3(G4 / 128, ROWS / 64), 256, 4 * E_STG2>>>();
    for (int t = 0; t < L_N; t++)
        lstm_step2<<<dim3(G4 / 64, P_N / 64), 256, 4 * L_STG2>>>(t);
    // seq_len==1 attention: softmax == 1, ctx == v; q/k projections are dead code
    gemm_proj_bf<<<dim3(H_DIM / 64, P_N / 64), 256, 4 * T_STG>>>(b_in + 2 * H_DIM, 0);
    gemm_proj_bf<<<dim3(H_DIM / 64, P_N / 64), 256, 4 * T_STG>>>(b_out, 1);
    colmax<<<H_DIM / 32, 256>>>();
    final_k<<<1, 256>>>(W_lin, b_lin, out);
}

// round 16
// speedup vs baseline: 1.0558x; 1.0087x over previous
#include <cuda_runtime.h>
#include <cuda_bf16.h>
#include <math.h>
#include <stdint.h>

#define P_N 256
#define L_N 64
#define I_DIM 512
#define H_DIM 1024
#define G4 4096
#define ROWS (P_N * L_N)  // 16384

// ---- scratch ----
__device__ __align__(128) __nv_bfloat16 g_xWb[(size_t)ROWS * G4];   // TIME-MAJOR row=t*256+p, bf16
__device__ __align__(128) uint8_t g_x8[(size_t)ROWS * I_DIM];       // fp8 e4m3, x*64
__device__ __align__(128) uint8_t g_Whh8[(size_t)G4 * H_DIM];       // fp8, permuted rows, w*64
__device__ __align__(128) uint8_t g_Wih8[(size_t)G4 * I_DIM];       // fp8, permuted rows, w*64
__device__ __align__(128) __nv_bfloat16 g_Wv_b[(size_t)H_DIM * H_DIM];
__device__ __align__(128) __nv_bfloat16 g_Wout_b[(size_t)H_DIM * H_DIM];
__device__ float g_bias_p[G4];
__device__ __align__(128) uint8_t g_h8[2][P_N * H_DIM];             // hidden fp8, h*16
__device__ float g_c[P_N * H_DIM];
__device__ __align__(128) __nv_bfloat16 g_final_b[P_N * H_DIM];     // sorted rows, bf16
__device__ __align__(128) __nv_bfloat16 g_vb[P_N * H_DIM];
__device__ float g_attn[P_N * H_DIM];
__device__ float g_pooled[H_DIM];
__device__ int g_perm[P_N];
__device__ int g_lens[P_N];      // lengths sorted descending

__device__ __forceinline__ float sigm(float x) { return 1.0f / (1.0f + expf(-x)); }

__device__ __forceinline__ uint32_t smem_u32(const void* p) {
    uint32_t a;
    asm("{ .reg .u64 t; cvta.to.shared.u64 t, %1; cvt.u32.u64 %0, t; }" : "=r"(a) : "l"(p));
    return a;
}
__device__ __forceinline__ uint32_t swz(uint32_t base, int row, int seg) {
    return base + (uint32_t)row * 128u + (uint32_t)((seg ^ (row & 7)) << 4);
}
__device__ __forceinline__ void cpa16(uint32_t dst, const void* src) {
    asm volatile("cp.async.ca.shared.global [%0], [%1], 16;" :: "r"(dst), "l"(src) : "memory");
}
#define CP_COMMIT() asm volatile("cp.async.commit_group;" ::: "memory")
#define CP_WAIT(n)  asm volatile("cp.async.wait_group " #n ";" ::: "memory")
#define LDM_X4(r0, r1, r2, r3, a)                                                       \
    asm volatile("ldmatrix.sync.aligned.m8n8.x4.shared.b16 {%0,%1,%2,%3}, [%4];"        \
                 : "=r"(r0), "=r"(r1), "=r"(r2), "=r"(r3) : "r"(a))

__device__ __forceinline__ void mmafp8(float* c, const uint32_t* a, const uint32_t* b) {
    asm volatile(
        "mma.sync.aligned.m16n8k32.row.col.f32.e4m3.e4m3.f32 "
        "{%0,%1,%2,%3}, {%4,%5,%6,%7}, {%8,%9}, {%0,%1,%2,%3};"
        : "+f"(c[0]), "+f"(c[1]), "+f"(c[2]), "+f"(c[3])
        : "r"(a[0]), "r"(a[1]), "r"(a[2]), "r"(a[3]), "r"(b[0]), "r"(b[1]));
}
__device__ __forceinline__ void mmabf(float* c, const uint32_t* a, const uint32_t* b) {
    asm volatile(
        "mma.sync.aligned.m16n8k16.row.col.f32.bf16.bf16.f32 "
        "{%0,%1,%2,%3}, {%4,%5,%6,%7}, {%8,%9}, {%0,%1,%2,%3};"
        : "+f"(c[0]), "+f"(c[1]), "+f"(c[2]), "+f"(c[3])
        : "r"(a[0]), "r"(a[1]), "r"(a[2]), "r"(a[3]), "r"(b[0]), "r"(b[1]));
}

// pack 4 floats -> 4 e4m3 bytes; first cvt operand lands in HIGH byte
__device__ __forceinline__ uint32_t pack_e4m3(float a, float b, float c, float d) {
    uint16_t lo, hi;
    asm("cvt.rn.satfinite.e4m3x2.f32 %0, %1, %2;" : "=h"(lo) : "f"(b), "f"(a));
    asm("cvt.rn.satfinite.e4m3x2.f32 %0, %1, %2;" : "=h"(hi) : "f"(d), "f"(c));
    return (uint32_t)lo | ((uint32_t)hi << 16);
}
__device__ __forceinline__ uint16_t pack2_e4m3(float a, float b) {
    uint16_t lo;
    asm("cvt.rn.satfinite.e4m3x2.f32 %0, %1, %2;" : "=h"(lo) : "f"(b), "f"(a));
    return lo;
}

// =================== prep ===================
__global__ void sort_paths(const int* __restrict__ lengths) {
    __shared__ int cnt[L_N + 1];
    const int tid = threadIdx.x;
    if (tid <= L_N) cnt[tid] = 0;
    __syncthreads();
    const int len = lengths[tid];
    atomicAdd(&cnt[len], 1);
    __syncthreads();
    if (tid == 0) {
        int acc = 0;
        for (int l = L_N; l >= 1; l--) { const int c = cnt[l]; cnt[l] = acc; acc += c; }
    }
    __syncthreads();
    const int pos = atomicAdd(&cnt[len], 1);
    g_perm[pos] = tid;
    g_lens[pos] = len;
}

// fused: blocks [0,4096) permute+fp8 LSTM weights; [4096,6144) convert Wv/Wout to bf16
__global__ void permute_weights(const float* __restrict__ Whh, const float* __restrict__ Wih,
                                const float* __restrict__ b_ih, const float* __restrict__ b_hh,
                                const float* __restrict__ Wv, const float* __restrict__ Wout) {
    const int r = blockIdx.x;
    if (r < G4) {
        const int q = (r >> 3) & 3;
        const int j = (r >> 5) * 8 + (r & 7);
        const int orig = q * H_DIM + j;
        const float4* s1 = (const float4*)(Whh + (size_t)orig * H_DIM);
        uint32_t* d1 = (uint32_t*)(g_Whh8 + (size_t)r * H_DIM);
        for (int i = threadIdx.x; i < H_DIM / 4; i += blockDim.x) {
            const float4 v = s1[i];
            d1[i] = pack_e4m3(v.x * 64.f, v.y * 64.f, v.z * 64.f, v.w * 64.f);
        }
        const float4* s2 = (const float4*)(Wih + (size_t)orig * I_DIM);
        uint32_t* d2 = (uint32_t*)(g_Wih8 + (size_t)r * I_DIM);
        for (int i = threadIdx.x; i < I_DIM / 4; i += blockDim.x) {
            const float4 v = s2[i];
            d2[i] = pack_e4m3(v.x * 64.f, v.y * 64.f, v.z * 64.f, v.w * 64.f);
        }
        if (threadIdx.x == 0) g_bias_p[r] = b_ih[orig] + b_hh[orig];
    } else {
        const int rc = r - G4;              // 0..2047
        const int rr = rc & 1023;
        const float4* s = (const float4*)(((rc < 1024) ? Wv : Wout) + (size_t)rr * H_DIM);
        __nv_bfloat162* d = (__nv_bfloat162*)(((rc < 1024) ? g_Wv_b : g_Wout_b) + (size_t)rr * H_DIM);
        for (int i = threadIdx.x; i < H_DIM / 4; i += blockDim.x) {
            const float4 v = s[i];
            d[i * 2 + 0] = __floats2bfloat162_rn(v.x, v.y);
            d[i * 2 + 1] = __floats2bfloat162_rn(v.z, v.w);
        }
    }
}

// gather time-major fp8
__global__ void gather_emb(const int* __restrict__ paths, const float* __restrict__ emb) {
    const int row = blockIdx.x * 2 + (threadIdx.x >> 7);
    const int k4 = (threadIdx.x & 127) * 4;
    const int t = row >> 8, p = row & 255;
    const int tok = paths[g_perm[p] * L_N + t];
    const float4 v = *(const float4*)(emb + (size_t)tok * I_DIM + k4);
    *(uint32_t*)(g_x8 + (size_t)row * I_DIM + k4) =
        pack_e4m3(v.x * 64.f, v.y * 64.f, v.z * 64.f, v.w * 64.f);
}

// =================== embed GEMM (fp8, 64p x 128n tiles, per-(t,quarter) early-exit) ==============
// grid (32 n, 256 m). 8 warps 2m x 4n. K=512 fp8 (4 chunks of 128B). 4 stages x 24KB, occ 2.
#define E_STG2 24576  // A 8KB + B 16KB

__global__ void __launch_bounds__(256, 2) gemm_embed_bf() {
    if (g_lens[(blockIdx.y & 3) * 64] <= (int)(blockIdx.y >> 2)) return;

    extern __shared__ char sm[];
    const uint32_t sb = smem_u32(sm);
    const int tid = threadIdx.x;
    const int lane = tid & 31, wid = tid >> 5;
    const int wm = wid >> 2, wn = wid & 3;        // 2m x 4n
    const int gr = lane >> 2, tg = lane & 3;
    const int m0 = blockIdx.y * 64, n0 = blockIdx.x * 128;

    const int a_row_l = (lane & 7) + ((lane >> 3) & 1) * 8;
    const int a_seg_l = lane >> 4;
    const int b_row_l = wn * 32 + (lane & 7) + (lane >> 4) * 8;
    const int b_seg_l = (lane >> 3) & 1;

    float cfr[2][4][4];
    #pragma unroll
    for (int a = 0; a < 2; a++)
        #pragma unroll
        for (int b = 0; b < 4; b++)
            #pragma unroll
            for (int c = 0; c < 4; c++) cfr[a][b][c] = 0.0f;

    #define E_ISSUE(cc) do {                                                            \
        const uint32_t ab = sb + ((cc) & 3) * E_STG2;                                   \
        const uint32_t bb = ab + 8192;                                                  \
        const int k0 = (cc) * 128;                                                      \
        _Pragma("unroll")                                                               \
        for (int i = 0; i < 2; i++) {                                                   \
            const int idx = tid + i * 256;                                              \
            const int row = idx >> 3, seg = idx & 7;                                    \
            cpa16(swz(ab, row, seg), g_x8 + (size_t)(m0 + row) * I_DIM + k0 + seg * 16);\
        }                                                                               \
        _Pragma("unroll")                                                               \
        for (int i = 0; i < 4; i++) {                                                   \
            const int idx = tid + i * 256;                                              \
            const int row = idx >> 3, seg = idx & 7;                                    \
            cpa16(swz(bb, row, seg),                                                    \
                  g_Wih8 + (size_t)(n0 + row) * I_DIM + k0 + seg * 16);                 \
        }                                                                               \
        CP_COMMIT();                                                                    \
    } while (0)

    E_ISSUE(0); E_ISSUE(1); E_ISSUE(2);

    for (int ch = 0; ch < 4; ch++) {
        if (ch <= 1) CP_WAIT(2);
        else if (ch == 2) CP_WAIT(1);
        else CP_WAIT(0);
        __syncthreads();
        if (ch + 3 < 4) E_ISSUE(ch + 3);

        const uint32_t ab = sb + (ch & 3) * E_STG2;
        const uint32_t bb = ab + 8192;
        #pragma unroll
        for (int s = 0; s < 4; s++) {
            uint32_t af[2][4], bf[4][2];
            #pragma unroll
            for (int mf = 0; mf < 2; mf++)
                LDM_X4(af[mf][0], af[mf][1], af[mf][2], af[mf][3],
                       swz(ab, wm * 32 + mf * 16 + a_row_l, 2 * s + a_seg_l));
            #pragma unroll
            for (int h = 0; h < 2; h++)
                LDM_X4(bf[2 * h][0], bf[2 * h][1], bf[2 * h + 1][0], bf[2 * h + 1][1],
                       swz(bb, b_row_l + h * 16, 2 * s + b_seg_l));
            #pragma unroll
            for (int mf = 0; mf < 2; mf++)
                #pragma unroll
                for (int nf = 0; nf < 4; nf++)
                    mmafp8(cfr[mf][nf], af[mf], bf[nf]);
        }
    }
    #undef E_ISSUE

    const int colw = n0 + wn * 32;
    const float inv = 1.0f / 4096.0f;
    #pragma unroll
    for (int mf = 0; mf < 2; mf++) {
        #pragma unroll
        for (int rr = 0; rr < 2; rr++) {
            const int row = m0 + wm * 32 + mf * 16 + gr + rr * 8;
            __nv_bfloat16* orow = g_xWb + (size_t)row * G4 + colw;
            #pragma unroll
            for (int q = 0; q < 4; q++) {
                const int cl = q * 8 + 2 * tg;
                const float2 bv = *(const float2*)&g_bias_p[colw + cl];
                *(__nv_bfloat162*)(orow + cl) = __floats2bfloat162_rn(
                    cfr[mf][q][rr * 2 + 0] * inv + bv.x, cfr[mf][q][rr * 2 + 1] * inv + bv.y);
            }
        }
    }
}

// =================== LSTM step 0 (h_prev == 0: gates = xW exactly; no GEMM) ===================
// grid 256 (p), 512 threads (jpair = tid). Writes g_c, g_h8[1], g_final_b (len==1).
// Replaces both zero_hc and the t=0 GEMM step.
__global__ void lstm_step0() {
    const int p = blockIdx.x;
    const int tid = threadIdx.x;                  // 0..511
    const int jg = tid >> 2;                      // 0..127 -> col group jg*32
    const int jl = (tid & 3) * 2;                 // 0,2,4,6
    const int colw = jg * 32;
    const int j = jg * 8 + jl;                    // h-col of element 0

    const size_t xb = (size_t)p * G4 + colw;      // t=0 rows are 0..255
    float2 xw[4];
    #pragma unroll
    for (int q = 0; q < 4; q++)
        xw[q] = __bfloat1622float2(*(const __nv_bfloat162*)&g_xWb[xb + q * 8 + jl]);

    // c_old == 0
    const float c0 = sigm(xw[0].x) * tanhf(xw[2].x);
    const float c1 = sigm(xw[0].y) * tanhf(xw[2].y);
    const float h0 = sigm(xw[3].x) * tanhf(c0);
    const float h1 = sigm(xw[3].y) * tanhf(c1);

    const int ci = p * H_DIM + j;
    *(float2*)&g_c[ci] = make_float2(c0, c1);
    *(uint16_t*)&g_h8[1][ci] = pack2_e4m3(h0 * 16.f, h1 * 16.f);
    if (g_lens[p] == 1)
        *(__nv_bfloat162*)&g_final_b[ci] = __floats2bfloat162_rn(h0, h1);
}

// =================== LSTM step (fp8, proven: 64x64 tiles, 128B chunks, 4 stages, occ 2) =====
// grid (64 n, 4 m) = 256 CTAs, 8 warps 4m x 2n. K=1024 fp8 (8 chunks of 128B).
#define L_STG2 16384  // A 8KB + B 8KB

__global__ void __launch_bounds__(256, 2) lstm_step2(const int step) {
    const int m0 = blockIdx.y * 64;
    if (g_lens[m0] <= step) return;

    extern __shared__ char sm[];
    const uint32_t sb = smem_u32(sm);
    const int tid = threadIdx.x;
    const int lane = tid & 31, wid = tid >> 5;
    const int wm = wid & 3, wn = wid >> 2;        // 4m x 2n
    const int gr = lane >> 2, tg = lane & 3;
    const int n0 = blockIdx.x * 64;

    const uint8_t* __restrict__ A_g = g_h8[step & 1];
    uint8_t* __restrict__ h_next = g_h8[(step & 1) ^ 1];

    const int a_row_l = (lane & 7) + ((lane >> 3) & 1) * 8;
    const int a_seg_l = lane >> 4;
    const int b_row_l = wn * 32 + (lane & 7) + (lane >> 4) * 8;
    const int b_seg_l = (lane >> 3) & 1;

    float cfr[4][4];
    #pragma unroll
    for (int b = 0; b < 4; b++)
        #pragma unroll
        for (int c = 0; c < 4; c++) cfr[b][c] = 0.0f;

    #define L_ISSUE(cc) do {                                                            \
        const uint32_t ab = sb + ((cc) & 3) * L_STG2;                                   \
        const uint32_t bb = ab + 8192;                                                  \
        const int k0 = (cc) * 128;                                                      \
        _Pragma("unroll")                                                               \
        for (int i = 0; i < 2; i++) {                                                   \
            const int idx = tid + i * 256;                                              \
            const int row = idx >> 3, seg = idx & 7;                                    \
            cpa16(swz(ab, row, seg), A_g + (size_t)(m0 + row) * H_DIM + k0 + seg * 16); \
            cpa16(swz(bb, row, seg),                                                    \
                  g_Whh8 + (size_t)(n0 + row) * H_DIM + k0 + seg * 16);                 \
        }                                                                               \
        CP_COMMIT();                                                                    \
    } while (0)

    L_ISSUE(0); L_ISSUE(1); L_ISSUE(2);

    for (int ch = 0; ch < 8; ch++) {
        if (ch <= 5) CP_WAIT(2);
        else if (ch == 6) CP_WAIT(1);
        else CP_WAIT(0);
        __syncthreads();
        if (ch + 3 < 8) L_ISSUE(ch + 3);

        const uint32_t ab = sb + (ch & 3) * L_STG2;
        const uint32_t bb = ab + 8192;
        #pragma unroll
        for (int s = 0; s < 4; s++) {
            uint32_t af[4], bf[4][2];
            LDM_X4(af[0], af[1], af[2], af[3],
                   swz(ab, wm * 16 + a_row_l, 2 * s + a_seg_l));
            #pragma unroll
            for (int h = 0; h < 2; h++)
                LDM_X4(bf[2 * h][0], bf[2 * h][1], bf[2 * h + 1][0], bf[2 * h + 1][1],
                       swz(bb, b_row_l + h * 16, 2 * s + b_seg_l));
            #pragma unroll
            for (int nf = 0; nf < 4; nf++)
                mmafp8(cfr[nf], af, bf[nf]);
        }
    }
    #undef L_ISSUE

    // epilogue: acc = (64 W)·(16 h) -> gate = acc/1024 + xw
    const int colw = n0 + wn * 32;
    const int jpair = (colw >> 5) * 8 + 2 * tg;
    const float inv = 1.0f / 1024.0f;
    #pragma unroll
    for (int rr = 0; rr < 2; rr++) {
        const int p = m0 + wm * 16 + gr + rr * 8;
        const int lenm1 = g_lens[p] - 1;
        const size_t xb = (size_t)(step * 256 + p) * G4 + colw;
        float2 xw[4];
        #pragma unroll
        for (int q = 0; q < 4; q++)
            xw[q] = __bfloat1622float2(*(const __nv_bfloat162*)&g_xWb[xb + q * 8 + 2 * tg]);

        const float gi0 = cfr[0][rr * 2 + 0] * inv + xw[0].x;
        const float gf0 = cfr[1][rr * 2 + 0] * inv + xw[1].x;
        const float gg0 = cfr[2][rr * 2 + 0] * inv + xw[2].x;
        const float go0 = cfr[3][rr * 2 + 0] * inv + xw[3].x;
        const float gi1 = cfr[0][rr * 2 + 1] * inv + xw[0].y;
        const float gf1 = cfr[1][rr * 2 + 1] * inv + xw[1].y;
        const float gg1 = cfr[2][rr * 2 + 1] * inv + xw[2].y;
        const float go1 = cfr[3][rr * 2 + 1] * inv + xw[3].y;

        const int ci = p * H_DIM + jpair;
        const float2 cold = *(const float2*)&g_c[ci];
        const float c0 = sigm(gf0) * cold.x + sigm(gi0) * tanhf(gg0);
        const float c1 = sigm(gf1) * cold.y + sigm(gi1) * tanhf(gg1);
        *(float2*)&g_c[ci] = make_float2(c0, c1);
        const float h0 = sigm(go0) * tanhf(c0);
        const float h1 = sigm(go1) * tanhf(c1);

        *(uint16_t*)&h_next[ci] = pack2_e4m3(h0 * 16.f, h1 * 16.f);
        if (lenm1 == step)
            *(__nv_bfloat162*)&g_final_b[ci] = __floats2bfloat162_rn(h0, h1);
    }
}

// =================== tail projections (bf16 mma, 64x64 tiles, occ 2) ===================
#define T_STG 16384  // A 8KB + B 8KB

__global__ void __launch_bounds__(256, 2) gemm_proj_bf(const float* __restrict__ bias,
                                                       const int sel) {
    extern __shared__ char sm[];
    const uint32_t sb = smem_u32(sm);
    const int tid = threadIdx.x;
    const int lane = tid & 31, wid = tid >> 5;
    const int wm = wid & 3, wn = wid >> 2;        // 4m x 2n
    const int gr = lane >> 2, tg = lane & 3;
    const int m0 = blockIdx.y * 64, n0 = blockIdx.x * 64;

    const __nv_bfloat16* __restrict__ A_g = (sel == 0) ? g_final_b : g_vb;
    const __nv_bfloat16* __restrict__ B_g = (sel == 0) ? g_Wv_b : g_Wout_b;

    const int a_row_l = (lane & 7) + ((lane >> 3) & 1) * 8;
    const int a_seg_l = lane >> 4;
    const int b_row_l = wn * 32 + (lane & 7) + (lane >> 4) * 8;
    const int b_seg_l = (lane >> 3) & 1;

    float cfr[4][4];
    #pragma unroll
    for (int b = 0; b < 4; b++)
        #pragma unroll
        for (int c = 0; c < 4; c++) cfr[b][c] = 0.0f;

    #define P_ISSUE(cc) do {                                                            \
        const uint32_t ab = sb + ((cc) & 3) * T_STG;                                    \
        const uint32_t bb = ab + 8192;                                                  \
        const int k0 = (cc) * 64;                                                       \
        _Pragma("unroll")                                                               \
        for (int i = 0; i < 2; i++) {                                                   \
            const int idx = tid + i * 256;                                              \
            const int row = idx >> 3, seg = idx & 7;                                    \
            cpa16(swz(ab, row, seg), A_g + (size_t)(m0 + row) * H_DIM + k0 + seg * 8);  \
            cpa16(swz(bb, row, seg), B_g + (size_t)(n0 + row) * H_DIM + k0 + seg * 8);  \
        }                                                                               \
        CP_COMMIT();                                                                    \
    } while (0)

    P_ISSUE(0); P_ISSUE(1); P_ISSUE(2);

    for (int ch = 0; ch < 16; ch++) {
        if (ch <= 13) CP_WAIT(2);
        else if (ch == 14) CP_WAIT(1);
        else CP_WAIT(0);
        __syncthreads();
        if (ch + 3 < 16) P_ISSUE(ch + 3);

        const uint32_t ab = sb + (ch & 3) * T_STG;
        const uint32_t bb = ab + 8192;
        #pragma unroll
        for (int s = 0; s < 4; s++) {
            uint32_t af[4], bf[4][2];
            LDM_X4(af[0], af[1], af[2], af[3],
                   swz(ab, wm * 16 + a_row_l, 2 * s + a_seg_l));
            #pragma unroll
            for (int h = 0; h < 2; h++)
                LDM_X4(bf[2 * h][0], bf[2 * h][1], bf[2 * h + 1][0], bf[2 * h + 1][1],
                       swz(bb, b_row_l + h * 16, 2 * s + b_seg_l));
            #pragma unroll
            for (int nf = 0; nf < 4; nf++)
                mmabf(cfr[nf], af, bf[nf]);
        }
    }
    #undef P_ISSUE

    const int colw = n0 + wn * 32;
    #pragma unroll
    for (int rr = 0; rr < 2; rr++) {
        const int row = m0 + wm * 16 + gr + rr * 8;
        #pragma unroll
        for (int q = 0; q < 4; q++) {
            const int cl = q * 8 + 2 * tg;
            const float2 bv = *(const float2*)&bias[colw + cl];
            const float v0 = cfr[q][rr * 2 + 0] + bv.x;
            const float v1 = cfr[q][rr * 2 + 1] + bv.y;
            if (sel == 0)
                *(__nv_bfloat162*)&g_vb[(size_t)row * H_DIM + colw + cl] =
                    __floats2bfloat162_rn(v0, v1);
            else
                *(float2*)&g_attn[(size_t)row * H_DIM + colw + cl] = make_float2(v0, v1);
        }
    }
}

// colmax: 32 blocks x 256 thr; 8 p-slices per column, smem reduce
__global__ void colmax() {
    __shared__ float red[8][32];
    const int j = blockIdx.x * 32 + (threadIdx.x & 31);
    const int sl = threadIdx.x >> 5;
    float m = -INFINITY;
    for (int p = sl * 32; p < sl * 32 + 32; p++)
        m = fmaxf(m, g_attn[(size_t)p * H_DIM + j]);
    red[sl][threadIdx.x & 31] = m;
    __syncthreads();
    if (sl == 0) {
        #pragma unroll
        for (int s = 1; s < 8; s++) m = fmaxf(m, red[s][threadIdx.x & 31]);
        g_pooled[j] = m;
    }
}

__global__ void final_k(const float* __restrict__ W_lin,
                        const float* __restrict__ b_lin, float* __restrict__ out)
{
    __shared__ float r0[256], r1[256];
    const int tid = threadIdx.x;
    float a0 = 0.0f, a1 = 0.0f;
    for (int j = tid; j < H_DIM; j += 256) {
        const float pv = g_pooled[j];
        a0 += pv * W_lin[j];
        a1 += pv * W_lin[H_DIM + j];
    }
    r0[tid] = a0; r1[tid] = a1;
    __syncthreads();
    for (int s = 128; s > 0; s >>= 1) {
        if (tid < s) { r0[tid] += r0[tid + s]; r1[tid] += r1[tid + s]; }
        __syncthreads();
    }
    if (tid == 0) {
        out[0] = sigm(r0[0] + b_lin[0]);
        out[1] = sigm(r1[0] + b_lin[1]);
    }
}

extern "C" void kernel_launch(void* const* d_in, const int* in_sizes, int n_in,
                              void* d_out, int out_size) {
    const int*   paths   = (const int*)d_in[0];
    const int*   lengths = (const int*)d_in[1];
    const float* emb     = (const float*)d_in[2];
    const float* W_ih    = (const float*)d_in[3];
    const float* W_hh    = (const float*)d_in[4];
    const float* b_ih    = (const float*)d_in[5];
    const float* b_hh    = (const float*)d_in[6];
    const float* W_in    = (const float*)d_in[7];
    const float* b_in    = (const float*)d_in[8];
    const float* W_out   = (const float*)d_in[9];
    const float* b_out   = (const float*)d_in[10];
    const float* W_lin   = (const float*)d_in[11];
    const float* b_lin   = (const float*)d_in[12];
    float* out = (float*)d_out;

    static int attr_done = 0;
    if (!attr_done) {
        cudaFuncSetAttribute(gemm_embed_bf, cudaFuncAttributeMaxDynamicSharedMemorySize, 4 * E_STG2);
        cudaFuncSetAttribute(lstm_step2,    cudaFuncAttributeMaxDynamicSharedMemorySize, 4 * L_STG2);
        cudaFuncSetAttribute(gemm_proj_bf,  cudaFuncAttributeMaxDynamicSharedMemorySize, 4 * T_STG);
        attr_done = 1;
    }

    sort_paths<<<1, 256>>>(lengths);
    permute_weights<<<6144, 128>>>(W_hh, W_ih, b_ih, b_hh,
                                   W_in + (size_t)2 * H_DIM * H_DIM, W_out);
    gather_emb<<<ROWS / 2, 256>>>(paths, emb);
    gemm_embed_bf<<<dim3(G4 / 128, ROWS / 64), 256, 4 * E_STG2>>>();
    // step 0: h_prev == 0 -> gates = xW exactly; also initializes c and the h ping-pong
    lstm_step0<<<P_N, 512>>>();
    for (int t = 1; t < L_N; t++)
        lstm_step2<<<dim3(G4 / 64, P_N / 64), 256, 4 * L_STG2>>>(t);
    // seq_len==1 attention: softmax == 1, ctx == v; q/k projections are dead code
    gemm_proj_bf<<<dim3(H_DIM / 64, P_N / 64), 256, 4 * T_STG>>>(b_in + 2 * H_DIM, 0);
    gemm_proj_bf<<<dim3(H_DIM / 64, P_N / 64), 256, 4 * T_STG>>>(b_out, 1);
    colmax<<<H_DIM / 32, 256>>>();
    final_k<<<1, 256>>>(W_lin, b_lin, out);
}

// round 17
// speedup vs baseline: 1.0586x; 1.0026x over previous
#include <cuda_runtime.h>
#include <cuda_bf16.h>
#include <math.h>
#include <stdint.h>

#define P_N 256
#define L_N 64
#define I_DIM 512
#define H_DIM 1024
#define G4 4096
#define ROWS (P_N * L_N)  // 16384

// ---- scratch ----
__device__ __align__(128) __nv_bfloat16 g_xWb[(size_t)ROWS * G4];   // TIME-MAJOR row=t*256+p, bf16
__device__ __align__(128) uint8_t g_x8[(size_t)ROWS * I_DIM];       // fp8 e4m3, x*64
__device__ __align__(128) uint8_t g_Whh8[(size_t)G4 * H_DIM];       // fp8, permuted rows, w*64
__device__ __align__(128) uint8_t g_Wih8[(size_t)G4 * I_DIM];       // fp8, permuted rows, w*64
__device__ __align__(128) __nv_bfloat16 g_Wv_b[(size_t)H_DIM * H_DIM];
__device__ __align__(128) __nv_bfloat16 g_Wout_b[(size_t)H_DIM * H_DIM];
__device__ float g_bias_p[G4];
__device__ __align__(128) uint8_t g_h8[2][P_N * H_DIM];             // hidden fp8, h*16
__device__ float g_c[P_N * H_DIM];
__device__ __align__(128) __nv_bfloat16 g_final_b[P_N * H_DIM];     // sorted rows, bf16
__device__ __align__(128) __nv_bfloat16 g_vb[P_N * H_DIM];
__device__ float g_attn[P_N * H_DIM];
__device__ float g_pooled[H_DIM];
__device__ int g_perm[P_N];
__device__ int g_lens[P_N];      // lengths sorted descending

__device__ __forceinline__ float sigm(float x) { return 1.0f / (1.0f + expf(-x)); }

__device__ __forceinline__ uint32_t smem_u32(const void* p) {
    uint32_t a;
    asm("{ .reg .u64 t; cvta.to.shared.u64 t, %1; cvt.u32.u64 %0, t; }" : "=r"(a) : "l"(p));
    return a;
}
__device__ __forceinline__ uint32_t swz(uint32_t base, int row, int seg) {
    return base + (uint32_t)row * 128u + (uint32_t)((seg ^ (row & 7)) << 4);
}
__device__ __forceinline__ void cpa16(uint32_t dst, const void* src) {
    asm volatile("cp.async.ca.shared.global [%0], [%1], 16;" :: "r"(dst), "l"(src) : "memory");
}
#define CP_COMMIT() asm volatile("cp.async.commit_group;" ::: "memory")
#define CP_WAIT(n)  asm volatile("cp.async.wait_group " #n ";" ::: "memory")
#define LDM_X4(r0, r1, r2, r3, a)                                                       \
    asm volatile("ldmatrix.sync.aligned.m8n8.x4.shared.b16 {%0,%1,%2,%3}, [%4];"        \
                 : "=r"(r0), "=r"(r1), "=r"(r2), "=r"(r3) : "r"(a))

__device__ __forceinline__ void mmafp8(float* c, const uint32_t* a, const uint32_t* b) {
    asm volatile(
        "mma.sync.aligned.m16n8k32.row.col.f32.e4m3.e4m3.f32 "
        "{%0,%1,%2,%3}, {%4,%5,%6,%7}, {%8,%9}, {%0,%1,%2,%3};"
        : "+f"(c[0]), "+f"(c[1]), "+f"(c[2]), "+f"(c[3])
        : "r"(a[0]), "r"(a[1]), "r"(a[2]), "r"(a[3]), "r"(b[0]), "r"(b[1]));
}
__device__ __forceinline__ void mmabf(float* c, const uint32_t* a, const uint32_t* b) {
    asm volatile(
        "mma.sync.aligned.m16n8k16.row.col.f32.bf16.bf16.f32 "
        "{%0,%1,%2,%3}, {%4,%5,%6,%7}, {%8,%9}, {%0,%1,%2,%3};"
        : "+f"(c[0]), "+f"(c[1]), "+f"(c[2]), "+f"(c[3])
        : "r"(a[0]), "r"(a[1]), "r"(a[2]), "r"(a[3]), "r"(b[0]), "r"(b[1]));
}

// pack 4 floats -> 4 e4m3 bytes; first cvt operand lands in HIGH byte
__device__ __forceinline__ uint32_t pack_e4m3(float a, float b, float c, float d) {
    uint16_t lo, hi;
    asm("cvt.rn.satfinite.e4m3x2.f32 %0, %1, %2;" : "=h"(lo) : "f"(b), "f"(a));
    asm("cvt.rn.satfinite.e4m3x2.f32 %0, %1, %2;" : "=h"(hi) : "f"(d), "f"(c));
    return (uint32_t)lo | ((uint32_t)hi << 16);
}
__device__ __forceinline__ uint16_t pack2_e4m3(float a, float b) {
    uint16_t lo;
    asm("cvt.rn.satfinite.e4m3x2.f32 %0, %1, %2;" : "=h"(lo) : "f"(b), "f"(a));
    return lo;
}

// =================== prep ===================
__global__ void sort_paths(const int* __restrict__ lengths) {
    __shared__ int cnt[L_N + 1];
    const int tid = threadIdx.x;
    if (tid <= L_N) cnt[tid] = 0;
    __syncthreads();
    const int len = lengths[tid];
    atomicAdd(&cnt[len], 1);
    __syncthreads();
    if (tid == 0) {
        int acc = 0;
        for (int l = L_N; l >= 1; l--) { const int c = cnt[l]; cnt[l] = acc; acc += c; }
    }
    __syncthreads();
    const int pos = atomicAdd(&cnt[len], 1);
    g_perm[pos] = tid;
    g_lens[pos] = len;
}

// fused: blocks [0,4096) permute+fp8 LSTM weights; [4096,6144) convert Wv/Wout to bf16
__global__ void permute_weights(const float* __restrict__ Whh, const float* __restrict__ Wih,
                                const float* __restrict__ b_ih, const float* __restrict__ b_hh,
                                const float* __restrict__ Wv, const float* __restrict__ Wout) {
    const int r = blockIdx.x;
    if (r < G4) {
        const int q = (r >> 3) & 3;
        const int j = (r >> 5) * 8 + (r & 7);
        const int orig = q * H_DIM + j;
        const float4* s1 = (const float4*)(Whh + (size_t)orig * H_DIM);
        uint32_t* d1 = (uint32_t*)(g_Whh8 + (size_t)r * H_DIM);
        for (int i = threadIdx.x; i < H_DIM / 4; i += blockDim.x) {
            const float4 v = s1[i];
            d1[i] = pack_e4m3(v.x * 64.f, v.y * 64.f, v.z * 64.f, v.w * 64.f);
        }
        const float4* s2 = (const float4*)(Wih + (size_t)orig * I_DIM);
        uint32_t* d2 = (uint32_t*)(g_Wih8 + (size_t)r * I_DIM);
        for (int i = threadIdx.x; i < I_DIM / 4; i += blockDim.x) {
            const float4 v = s2[i];
            d2[i] = pack_e4m3(v.x * 64.f, v.y * 64.f, v.z * 64.f, v.w * 64.f);
        }
        if (threadIdx.x == 0) g_bias_p[r] = b_ih[orig] + b_hh[orig];
    } else {
        const int rc = r - G4;              // 0..2047
        const int rr = rc & 1023;
        const float4* s = (const float4*)(((rc < 1024) ? Wv : Wout) + (size_t)rr * H_DIM);
        __nv_bfloat162* d = (__nv_bfloat162*)(((rc < 1024) ? g_Wv_b : g_Wout_b) + (size_t)rr * H_DIM);
        for (int i = threadIdx.x; i < H_DIM / 4; i += blockDim.x) {
            const float4 v = s[i];
            d[i * 2 + 0] = __floats2bfloat162_rn(v.x, v.y);
            d[i * 2 + 1] = __floats2bfloat162_rn(v.z, v.w);
        }
    }
}

// gather time-major fp8
__global__ void gather_emb(const int* __restrict__ paths, const float* __restrict__ emb) {
    const int row = blockIdx.x * 2 + (threadIdx.x >> 7);
    const int k4 = (threadIdx.x & 127) * 4;
    const int t = row >> 8, p = row & 255;
    const int tok = paths[g_perm[p] * L_N + t];
    const float4 v = *(const float4*)(emb + (size_t)tok * I_DIM + k4);
    *(uint32_t*)(g_x8 + (size_t)row * I_DIM + k4) =
        pack_e4m3(v.x * 64.f, v.y * 64.f, v.z * 64.f, v.w * 64.f);
}

// =================== embed GEMM (fp8, 64p x 128n tiles, per-(t,quarter) early-exit) ==============
// grid (32 n, 256 m). 8 warps 2m x 4n. K=512 fp8 (4 chunks of 128B). 4 stages x 24KB, occ 2.
// All swizzled addresses hoisted to registers; per-chunk cost = one add per op.
#define E_STG2 24576  // A 8KB + B 16KB

__global__ void __launch_bounds__(256, 2) gemm_embed_bf() {
    if (g_lens[(blockIdx.y & 3) * 64] <= (int)(blockIdx.y >> 2)) return;

    extern __shared__ char sm[];
    const uint32_t sb = smem_u32(sm);
    const int tid = threadIdx.x;
    const int lane = tid & 31, wid = tid >> 5;
    const int wm = wid >> 2, wn = wid & 3;        // 2m x 4n
    const int gr = lane >> 2, tg = lane & 3;
    const int m0 = blockIdx.y * 64, n0 = blockIdx.x * 128;

    // ---- loader: stable dst (swizzled) + src pointers ----
    const int lrow = tid >> 3, lseg = tid & 7;
    const uint32_t dA0 = swz(sb, lrow, lseg);
    const uint32_t dA1 = swz(sb, lrow + 32, lseg);
    uint32_t dB[4];
    #pragma unroll
    for (int i = 0; i < 4; i++) dB[i] = swz(sb + 8192, lrow + i * 32, lseg);
    const uint8_t* sA0 = g_x8 + (size_t)(m0 + lrow) * I_DIM + lseg * 16;
    const uint8_t* sA1 = g_x8 + (size_t)(m0 + lrow + 32) * I_DIM + lseg * 16;
    const uint8_t* sB[4];
    #pragma unroll
    for (int i = 0; i < 4; i++)
        sB[i] = g_Wih8 + (size_t)(n0 + lrow + i * 32) * I_DIM + lseg * 16;

    // ---- mainloop: stable ldmatrix addresses per s ----
    const int a_row_l = wm * 32 + (lane & 7) + ((lane >> 3) & 1) * 8;
    const int a_seg_l = lane >> 4;
    const int b_row_l = wn * 32 + (lane & 7) + (lane >> 4) * 8;
    const int b_seg_l = (lane >> 3) & 1;
    uint32_t lA[2][4], lB[2][4];
    #pragma unroll
    for (int s = 0; s < 4; s++) {
        lA[0][s] = swz(sb, a_row_l, 2 * s + a_seg_l);
        lA[1][s] = swz(sb, a_row_l + 16, 2 * s + a_seg_l);
        lB[0][s] = swz(sb + 8192, b_row_l, 2 * s + b_seg_l);
        lB[1][s] = swz(sb + 8192, b_row_l + 16, 2 * s + b_seg_l);
    }

    float cfr[2][4][4];
    #pragma unroll
    for (int a = 0; a < 2; a++)
        #pragma unroll
        for (int b = 0; b < 4; b++)
            #pragma unroll
            for (int c = 0; c < 4; c++) cfr[a][b][c] = 0.0f;

    #define E_ISSUE(cc) do {                                                            \
        const uint32_t so = ((cc) & 3) * E_STG2;                                        \
        const int k0 = (cc) * 128;                                                      \
        cpa16(dA0 + so, sA0 + k0);                                                      \
        cpa16(dA1 + so, sA1 + k0);                                                      \
        _Pragma("unroll")                                                               \
        for (int i = 0; i < 4; i++) cpa16(dB[i] + so, sB[i] + k0);                      \
        CP_COMMIT();                                                                    \
    } while (0)

    E_ISSUE(0); E_ISSUE(1); E_ISSUE(2);

    for (int ch = 0; ch < 4; ch++) {
        if (ch <= 1) CP_WAIT(2);
        else if (ch == 2) CP_WAIT(1);
        else CP_WAIT(0);
        __syncthreads();
        if (ch + 3 < 4) E_ISSUE(ch + 3);

        const uint32_t so = (ch & 3) * E_STG2;
        #pragma unroll
        for (int s = 0; s < 4; s++) {
            uint32_t af[2][4], bf[4][2];
            #pragma unroll
            for (int mf = 0; mf < 2; mf++)
                LDM_X4(af[mf][0], af[mf][1], af[mf][2], af[mf][3], lA[mf][s] + so);
            #pragma unroll
            for (int h = 0; h < 2; h++)
                LDM_X4(bf[2 * h][0], bf[2 * h][1], bf[2 * h + 1][0], bf[2 * h + 1][1],
                       lB[h][s] + so);
            #pragma unroll
            for (int mf = 0; mf < 2; mf++)
                #pragma unroll
                for (int nf = 0; nf < 4; nf++)
                    mmafp8(cfr[mf][nf], af[mf], bf[nf]);
        }
    }
    #undef E_ISSUE

    const int colw = n0 + wn * 32;
    const float inv = 1.0f / 4096.0f;
    #pragma unroll
    for (int mf = 0; mf < 2; mf++) {
        #pragma unroll
        for (int rr = 0; rr < 2; rr++) {
            const int row = m0 + wm * 32 + mf * 16 + gr + rr * 8;
            __nv_bfloat16* orow = g_xWb + (size_t)row * G4 + colw;
            #pragma unroll
            for (int q = 0; q < 4; q++) {
                const int cl = q * 8 + 2 * tg;
                const float2 bv = *(const float2*)&g_bias_p[colw + cl];
                *(__nv_bfloat162*)(orow + cl) = __floats2bfloat162_rn(
                    cfr[mf][q][rr * 2 + 0] * inv + bv.x, cfr[mf][q][rr * 2 + 1] * inv + bv.y);
            }
        }
    }
}

// =================== LSTM step 0 (h_prev == 0: gates = xW exactly; no GEMM) ===================
__global__ void lstm_step0() {
    const int p = blockIdx.x;
    const int tid = threadIdx.x;                  // 0..511
    const int jg = tid >> 2;                      // 0..127 -> col group jg*32
    const int jl = (tid & 3) * 2;                 // 0,2,4,6
    const int colw = jg * 32;
    const int j = jg * 8 + jl;

    const size_t xb = (size_t)p * G4 + colw;
    float2 xw[4];
    #pragma unroll
    for (int q = 0; q < 4; q++)
        xw[q] = __bfloat1622float2(*(const __nv_bfloat162*)&g_xWb[xb + q * 8 + jl]);

    const float c0 = sigm(xw[0].x) * tanhf(xw[2].x);
    const float c1 = sigm(xw[0].y) * tanhf(xw[2].y);
    const float h0 = sigm(xw[3].x) * tanhf(c0);
    const float h1 = sigm(xw[3].y) * tanhf(c1);

    const int ci = p * H_DIM + j;
    *(float2*)&g_c[ci] = make_float2(c0, c1);
    *(uint16_t*)&g_h8[1][ci] = pack2_e4m3(h0 * 16.f, h1 * 16.f);
    if (g_lens[p] == 1)
        *(__nv_bfloat162*)&g_final_b[ci] = __floats2bfloat162_rn(h0, h1);
}

// =================== LSTM step (fp8, 64x64 tiles, 128B chunks, 4 stages, occ 2) =====
// grid (64 n, 4 m) = 256 CTAs, 8 warps 4m x 2n. All addresses register-hoisted.
#define L_STG2 16384  // A 8KB + B 8KB

__global__ void __launch_bounds__(256, 2) lstm_step2(const int step) {
    const int m0 = blockIdx.y * 64;
    if (g_lens[m0] <= step) return;

    extern __shared__ char sm[];
    const uint32_t sb = smem_u32(sm);
    const int tid = threadIdx.x;
    const int lane = tid & 31, wid = tid >> 5;
    const int wm = wid & 3, wn = wid >> 2;        // 4m x 2n
    const int gr = lane >> 2, tg = lane & 3;
    const int n0 = blockIdx.x * 64;

    const uint8_t* __restrict__ A_g = g_h8[step & 1];
    uint8_t* __restrict__ h_next = g_h8[(step & 1) ^ 1];

    // ---- loader: stable dst + src ----
    const int lrow = tid >> 3, lseg = tid & 7;
    const uint32_t dA0 = swz(sb, lrow, lseg);
    const uint32_t dA1 = swz(sb, lrow + 32, lseg);
    const uint32_t dB0 = dA0 + 8192, dB1 = dA1 + 8192;
    const uint8_t* sA0 = A_g + (size_t)(m0 + lrow) * H_DIM + lseg * 16;
    const uint8_t* sA1 = A_g + (size_t)(m0 + lrow + 32) * H_DIM + lseg * 16;
    const uint8_t* sB0 = g_Whh8 + (size_t)(n0 + lrow) * H_DIM + lseg * 16;
    const uint8_t* sB1 = g_Whh8 + (size_t)(n0 + lrow + 32) * H_DIM + lseg * 16;

    // ---- mainloop: stable ldmatrix addresses per s ----
    const int a_row_l = wm * 16 + (lane & 7) + ((lane >> 3) & 1) * 8;
    const int a_seg_l = lane >> 4;
    const int b_row_l = wn * 32 + (lane & 7) + (lane >> 4) * 8;
    const int b_seg_l = (lane >> 3) & 1;
    uint32_t lA[4], lB0[4], lB1[4];
    #pragma unroll
    for (int s = 0; s < 4; s++) {
        lA[s] = swz(sb, a_row_l, 2 * s + a_seg_l);
        lB0[s] = swz(sb + 8192, b_row_l, 2 * s + b_seg_l);
        lB1[s] = swz(sb + 8192, b_row_l + 16, 2 * s + b_seg_l);
    }

    float cfr[4][4];
    #pragma unroll
    for (int b = 0; b < 4; b++)
        #pragma unroll
        for (int c = 0; c < 4; c++) cfr[b][c] = 0.0f;

    #define L_ISSUE(cc) do {                                                            \
        const uint32_t so = ((cc) & 3) * L_STG2;                                        \
        const int k0 = (cc) * 128;                                                      \
        cpa16(dA0 + so, sA0 + k0);                                                      \
        cpa16(dB0 + so, sB0 + k0);                                                      \
        cpa16(dA1 + so, sA1 + k0);                                                      \
        cpa16(dB1 + so, sB1 + k0);                                                      \
        CP_COMMIT();                                                                    \
    } while (0)

    L_ISSUE(0); L_ISSUE(1); L_ISSUE(2);

    for (int ch = 0; ch < 8; ch++) {
        if (ch <= 5) CP_WAIT(2);
        else if (ch == 6) CP_WAIT(1);
        else CP_WAIT(0);
        __syncthreads();
        if (ch + 3 < 8) L_ISSUE(ch + 3);

        const uint32_t so = (ch & 3) * L_STG2;
        #pragma unroll
        for (int s = 0; s < 4; s++) {
            uint32_t af[4], bf[4][2];
            LDM_X4(af[0], af[1], af[2], af[3], lA[s] + so);
            LDM_X4(bf[0][0], bf[0][1], bf[1][0], bf[1][1], lB0[s] + so);
            LDM_X4(bf[2][0], bf[2][1], bf[3][0], bf[3][1], lB1[s] + so);
            #pragma unroll
            for (int nf = 0; nf < 4; nf++)
                mmafp8(cfr[nf], af, bf[nf]);
        }
    }
    #undef L_ISSUE

    // epilogue: acc = (64 W)·(16 h) -> gate = acc/1024 + xw
    const int colw = n0 + wn * 32;
    const int jpair = (colw >> 5) * 8 + 2 * tg;
    const float inv = 1.0f / 1024.0f;
    #pragma unroll
    for (int rr = 0; rr < 2; rr++) {
        const int p = m0 + wm * 16 + gr + rr * 8;
        const int lenm1 = g_lens[p] - 1;
        const size_t xb = (size_t)(step * 256 + p) * G4 + colw;
        float2 xw[4];
        #pragma unroll
        for (int q = 0; q < 4; q++)
            xw[q] = __bfloat1622float2(*(const __nv_bfloat162*)&g_xWb[xb + q * 8 + 2 * tg]);

        const float gi0 = cfr[0][rr * 2 + 0] * inv + xw[0].x;
        const float gf0 = cfr[1][rr * 2 + 0] * inv + xw[1].x;
        const float gg0 = cfr[2][rr * 2 + 0] * inv + xw[2].x;
        const float go0 = cfr[3][rr * 2 + 0] * inv + xw[3].x;
        const float gi1 = cfr[0][rr * 2 + 1] * inv + xw[0].y;
        const float gf1 = cfr[1][rr * 2 + 1] * inv + xw[1].y;
        const float gg1 = cfr[2][rr * 2 + 1] * inv + xw[2].y;
        const float go1 = cfr[3][rr * 2 + 1] * inv + xw[3].y;

        const int ci = p * H_DIM + jpair;
        const float2 cold = *(const float2*)&g_c[ci];
        const float c0 = sigm(gf0) * cold.x + sigm(gi0) * tanhf(gg0);
        const float c1 = sigm(gf1) * cold.y + sigm(gi1) * tanhf(gg1);
        *(float2*)&g_c[ci] = make_float2(c0, c1);
        const float h0 = sigm(go0) * tanhf(c0);
        const float h1 = sigm(go1) * tanhf(c1);

        *(uint16_t*)&h_next[ci] = pack2_e4m3(h0 * 16.f, h1 * 16.f);
        if (lenm1 == step)
            *(__nv_bfloat162*)&g_final_b[ci] = __floats2bfloat162_rn(h0, h1);
    }
}

// =================== tail projections (bf16 mma, 64x64 tiles, occ 2) ===================
#define T_STG 16384  // A 8KB + B 8KB

__global__ void __launch_bounds__(256, 2) gemm_proj_bf(const float* __restrict__ bias,
                                                       const int sel) {
    extern __shared__ char sm[];
    const uint32_t sb = smem_u32(sm);
    const int tid = threadIdx.x;
    const int lane = tid & 31, wid = tid >> 5;
    const int wm = wid & 3, wn = wid >> 2;        // 4m x 2n
    const int gr = lane >> 2, tg = lane & 3;
    const int m0 = blockIdx.y * 64, n0 = blockIdx.x * 64;

    const __nv_bfloat16* __restrict__ A_g = (sel == 0) ? g_final_b : g_vb;
    const __nv_bfloat16* __restrict__ B_g = (sel == 0) ? g_Wv_b : g_Wout_b;

    const int lrow = tid >> 3, lseg = tid & 7;
    const uint32_t dA0 = swz(sb, lrow, lseg);
    const uint32_t dA1 = swz(sb, lrow + 32, lseg);
    const uint32_t dB0 = dA0 + 8192, dB1 = dA1 + 8192;
    const __nv_bfloat16* sA0 = A_g + (size_t)(m0 + lrow) * H_DIM + lseg * 8;
    const __nv_bfloat16* sA1 = A_g + (size_t)(m0 + lrow + 32) * H_DIM + lseg * 8;
    const __nv_bfloat16* sB0 = B_g + (size_t)(n0 + lrow) * H_DIM + lseg * 8;
    const __nv_bfloat16* sB1 = B_g + (size_t)(n0 + lrow + 32) * H_DIM + lseg * 8;

    const int a_row_l = wm * 16 + (lane & 7) + ((lane >> 3) & 1) * 8;
    const int a_seg_l = lane >> 4;
    const int b_row_l = wn * 32 + (lane & 7) + (lane >> 4) * 8;
    const int b_seg_l = (lane >> 3) & 1;
    uint32_t lA[4], lB0[4], lB1[4];
    #pragma unroll
    for (int s = 0; s < 4; s++) {
        lA[s] = swz(sb, a_row_l, 2 * s + a_seg_l);
        lB0[s] = swz(sb + 8192, b_row_l, 2 * s + b_seg_l);
        lB1[s] = swz(sb + 8192, b_row_l + 16, 2 * s + b_seg_l);
    }

    float cfr[4][4];
    #pragma unroll
    for (int b = 0; b < 4; b++)
        #pragma unroll
        for (int c = 0; c < 4; c++) cfr[b][c] = 0.0f;

    #define P_ISSUE(cc) do {                                                            \
        const uint32_t so = ((cc) & 3) * T_STG;                                         \
        const int k0 = (cc) * 64;                                                       \
        cpa16(dA0 + so, sA0 + k0);                                                      \
        cpa16(dB0 + so, sB0 + k0);                                                      \
        cpa16(dA1 + so, sA1 + k0);                                                      \
        cpa16(dB1 + so, sB1 + k0);                                                      \
        CP_COMMIT();                                                                    \
    } while (0)

    P_ISSUE(0); P_ISSUE(1); P_ISSUE(2);

    for (int ch = 0; ch < 16; ch++) {
        if (ch <= 13) CP_WAIT(2);
        else if (ch == 14) CP_WAIT(1);
        else CP_WAIT(0);
        __syncthreads();
        if (ch + 3 < 16) P_ISSUE(ch + 3);

        const uint32_t so = (ch & 3) * T_STG;
        #pragma unroll
        for (int s = 0; s < 4; s++) {
            uint32_t af[4], bf[4][2];
            LDM_X4(af[0], af[1], af[2], af[3], lA[s] + so);
            LDM_X4(bf[0][0], bf[0][1], bf[1][0], bf[1][1], lB0[s] + so);
            LDM_X4(bf[2][0], bf[2][1], bf[3][0], bf[3][1], lB1[s] + so);
            #pragma unroll
            for (int nf = 0; nf < 4; nf++)
                mmabf(cfr[nf], af, bf[nf]);
        }
    }
    #undef P_ISSUE

    const int colw = n0 + wn * 32;
    #pragma unroll
    for (int rr = 0; rr < 2; rr++) {
        const int row = m0 + wm * 16 + gr + rr * 8;
        #pragma unroll
        for (int q = 0; q < 4; q++) {
            const int cl = q * 8 + 2 * tg;
            const float2 bv = *(const float2*)&bias[colw + cl];
            const float v0 = cfr[q][rr * 2 + 0] + bv.x;
            const float v1 = cfr[q][rr * 2 + 1] + bv.y;
            if (sel == 0)
                *(__nv_bfloat162*)&g_vb[(size_t)row * H_DIM + colw + cl] =
                    __floats2bfloat162_rn(v0, v1);
            else
                *(float2*)&g_attn[(size_t)row * H_DIM + colw + cl] = make_float2(v0, v1);
        }
    }
}

// colmax: 32 blocks x 256 thr; 8 p-slices per column, smem reduce
__global__ void colmax() {
    __shared__ float red[8][32];
    const int j = blockIdx.x * 32 + (threadIdx.x & 31);
    const int sl = threadIdx.x >> 5;
    float m = -INFINITY;
    for (int p = sl * 32; p < sl * 32 + 32; p++)
        m = fmaxf(m, g_attn[(size_t)p * H_DIM + j]);
    red[sl][threadIdx.x & 31] = m;
    __syncthreads();
    if (sl == 0) {
        #pragma unroll
        for (int s = 1; s < 8; s++) m = fmaxf(m, red[s][threadIdx.x & 31]);
        g_pooled[j] = m;
    }
}

__global__ void final_k(const float* __restrict__ W_lin,
                        const float* __restrict__ b_lin, float* __restrict__ out)
{
    __shared__ float r0[256], r1[256];
    const int tid = threadIdx.x;
    float a0 = 0.0f, a1 = 0.0f;
    for (int j = tid; j < H_DIM; j += 256) {
        const float pv = g_pooled[j];
        a0 += pv * W_lin[j];
        a1 += pv * W_lin[H_DIM + j];
    }
    r0[tid] = a0; r1[tid] = a1;
    __syncthreads();
    for (int s = 128; s > 0; s >>= 1) {
        if (tid < s) { r0[tid] += r0[tid + s]; r1[tid] += r1[tid + s]; }
        __syncthreads();
    }
    if (tid == 0) {
        out[0] = sigm(r0[0] + b_lin[0]);
        out[1] = sigm(r1[0] + b_lin[1]);
    }
}

extern "C" void kernel_launch(void* const* d_in, const int* in_sizes, int n_in,
                              void* d_out, int out_size) {
    const int*   paths   = (const int*)d_in[0];
    const int*   lengths = (const int*)d_in[1];
    const float* emb     = (const float*)d_in[2];
    const float* W_ih    = (const float*)d_in[3];
    const float* W_hh    = (const float*)d_in[4];
    const float* b_ih    = (const float*)d_in[5];
    const float* b_hh    = (const float*)d_in[6];
    const float* W_in    = (const float*)d_in[7];
    const float* b_in    = (const float*)d_in[8];
    const float* W_out   = (const float*)d_in[9];
    const float* b_out   = (const float*)d_in[10];
    const float* W_lin   = (const float*)d_in[11];
    const float* b_lin   = (const float*)d_in[12];
    float* out = (float*)d_out;

    static int attr_done = 0;
    if (!attr_done) {
        cudaFuncSetAttribute(gemm_embed_bf, cudaFuncAttributeMaxDynamicSharedMemorySize, 4 * E_STG2);
        cudaFuncSetAttribute(lstm_step2,    cudaFuncAttributeMaxDynamicSharedMemorySize, 4 * L_STG2);
        cudaFuncSetAttribute(gemm_proj_bf,  cudaFuncAttributeMaxDynamicSharedMemorySize, 4 * T_STG);
        attr_done = 1;
    }

    sort_paths<<<1, 256>>>(lengths);
    permute_weights<<<6144, 128>>>(W_hh, W_ih, b_ih, b_hh,
                                   W_in + (size_t)2 * H_DIM * H_DIM, W_out);
    gather_emb<<<ROWS / 2, 256>>>(paths, emb);
    gemm_embed_bf<<<dim3(G4 / 128, ROWS / 64), 256, 4 * E_STG2>>>();
    // step 0: h_prev == 0 -> gates = xW exactly; also initializes c and the h ping-pong
    lstm_step0<<<P_N, 512>>>();
    for (int t = 1; t < L_N; t++)
        lstm_step2<<<dim3(G4 / 64, P_N / 64), 256, 4 * L_STG2>>>(t);
    // seq_len==1 attention: softmax == 1, ctx == v; q/k projections are dead code
    gemm_proj_bf<<<dim3(H_DIM / 64, P_N / 64), 256, 4 * T_STG>>>(b_in + 2 * H_DIM, 0);
    gemm_proj_bf<<<dim3(H_DIM / 64, P_N / 64), 256, 4 * T_STG>>>(b_out, 1);
    colmax<<<H_DIM / 32, 256>>>();
    final_k<<<1, 256>>>(W_lin, b_lin, out);
}